// round 10
// baseline (speedup 1.0000x reference)
#include <cuda_runtime.h>
#include <cuda_bf16.h>
#include <math.h>
#include <stdint.h>

// ---------------------------------------------------------------------------
// Shapes: Ns=Nr=100000, E=600000, D=128, A=8, S=64, H=128
// ---------------------------------------------------------------------------
#define MAX_E 600000
#define MAX_N 100000

// Scratch (__device__ globals; allocation-free rule)
__device__ float g_sf [(size_t)MAX_N * 128];   // sender features
__device__ float g_sc [(size_t)MAX_N * 128];   // receiver self connection
__device__ float g_rf [(size_t)MAX_N * 128];   // scattered receiver features
__device__ float g_ang[(size_t)MAX_N];         // receiver angle
// Prepped weights, bf16; 256KB slots.
// slots 0/1: fc1 hi/lo  n-major [n][64]
// slots 2/3: fc2 hi/lo  n-major [n][128]
// slots 4/5: lin1 hi/lo v-major [v][n][k]  (8 x 128 x 128)
// slots 6/7: sc   hi/lo v-major
// slots 8/9: lin2 hi/lo v-major
__device__ __align__(1024) uint8_t g_wp[10][262144];

// ---------------------------------------------------------------------------
// mma.sync / ldmatrix / cp.async helpers (sm_80+/sm_90, no arch-a gating)
// ---------------------------------------------------------------------------
__device__ __forceinline__ uint32_t smem_u32(const void* p) {
    uint32_t a;
    asm("{ .reg .u64 t; cvta.to.shared.u64 t, %1; cvt.u32.u64 %0, t; }" : "=r"(a) : "l"(p));
    return a;
}

__device__ __forceinline__ void mma16816(float* d, const uint32_t* a, const uint32_t* b) {
    asm volatile(
        "mma.sync.aligned.m16n8k16.row.col.f32.bf16.bf16.f32 "
        "{%0,%1,%2,%3}, {%4,%5,%6,%7}, {%8,%9}, {%0,%1,%2,%3};"
        : "+f"(d[0]), "+f"(d[1]), "+f"(d[2]), "+f"(d[3])
        : "r"(a[0]), "r"(a[1]), "r"(a[2]), "r"(a[3]), "r"(b[0]), "r"(b[1]));
}

__device__ __forceinline__ void ldsm4(uint32_t* r, uint32_t addr) {
    asm volatile("ldmatrix.sync.aligned.m8n8.x4.shared.b16 {%0,%1,%2,%3}, [%4];"
                 : "=r"(r[0]), "=r"(r[1]), "=r"(r[2]), "=r"(r[3]) : "r"(addr));
}

__device__ __forceinline__ void cp16(uint32_t s, const void* g) {
    asm volatile("cp.async.cg.shared.global [%0], [%1], 16;"
                 :: "r"(s), "l"(g) : "memory");
}
#define CP_COMMIT() asm volatile("cp.async.commit_group;" ::: "memory")
#define CP_WAIT0()  asm volatile("cp.async.wait_group 0;" ::: "memory")

// vector float2 reduction (PTX 8.1, sm_90+)
__device__ __forceinline__ void redv2(float* addr, float a, float b) {
    asm volatile("red.global.add.v2.f32 [%0], {%1, %2};" :: "l"(addr), "f"(a), "f"(b) : "memory");
}

// pack two fp32 -> bf16x2 (hi), and residual (lo)
__device__ __forceinline__ uint32_t pack_hi(float a, float b) {
    __nv_bfloat162 h = __float22bfloat162_rn(make_float2(a, b));
    return *(uint32_t*)&h;
}
__device__ __forceinline__ uint32_t pack_lo(float a, float b, uint32_t hp) {
    __nv_bfloat162 h = *(__nv_bfloat162*)&hp;
    float2 hf = __bfloat1622float2(h);
    __nv_bfloat162 l = __float22bfloat162_rn(make_float2(a - hf.x, b - hf.y));
    return *(uint32_t*)&l;
}

__device__ __forceinline__ float silu_n(float x) {
    return 1.679177f * x / (1.f + expf(-x));
}

// ---------------------------------------------------------------------------
// Merged weight prep (ONE launch)
// ---------------------------------------------------------------------------
__global__ void prep_all(const float* __restrict__ Wfc1, const float* __restrict__ Wfc2,
                         const float* __restrict__ Wl1,  const float* __restrict__ Wsc,
                         const float* __restrict__ Wl2,  uint8_t* __restrict__ wp)
{
    int idx = blockIdx.x * blockDim.x + threadIdx.x;
    if (idx < 4096) {                    // fc1
        int n = idx >> 5, kp = (idx & 31) << 1;
        float a = Wfc1[(size_t)kp * 128 + n];
        float b = Wfc1[(size_t)(kp + 1) * 128 + n];
        uint32_t h = pack_hi(a, b), l = pack_lo(a, b, h);
        ((uint32_t*)(wp))[n * 32 + (kp >> 1)] = h;
        ((uint32_t*)(wp + 262144))[n * 32 + (kp >> 1)] = l;
    } else if (idx < 12288) {            // fc2
        int i = idx - 4096;
        int n = i >> 6, kp = (i & 63) << 1;
        float a = Wfc2[(size_t)kp * 128 + n];
        float b = Wfc2[(size_t)(kp + 1) * 128 + n];
        uint32_t h = pack_hi(a, b), l = pack_lo(a, b, h);
        ((uint32_t*)(wp + 2 * 262144))[n * 64 + (kp >> 1)] = h;
        ((uint32_t*)(wp + 3 * 262144))[n * 64 + (kp >> 1)] = l;
    } else if (idx < 208896) {           // lin weights, v-major
        int i = idx - 12288;
        int w = i >> 16;                 // 0=lin1 1=sc 2=lin2
        int r = i & 65535;
        int v = r >> 13, n = (r >> 6) & 127, up = r & 63, u = up << 1;
        const float* W = (w == 0) ? Wl1 : (w == 1) ? Wsc : Wl2;
        float a = W[(size_t)(u * 8 + v) * 128 + n];
        float b = W[(size_t)((u + 1) * 8 + v) * 128 + n];
        uint32_t h = pack_hi(a, b), l = pack_lo(a, b, h);
        ((uint32_t*)(wp + (size_t)(4 + 2 * w) * 262144))[v * 8192 + n * 64 + up] = h;
        ((uint32_t*)(wp + (size_t)(5 + 2 * w) * 262144))[v * 8192 + n * 64 + up] = l;
    }
}

// ---------------------------------------------------------------------------
// fctp, low-smem high-occupancy version:
//   out[m,w] = scale * sum_{v,u} (Y[m,v]*X[m,u]) * Wv[u,w]
// Tile: 128 nodes x 128 cols, 8 warps, warp tile 32m x 64n.
// kc-outer (8 chunks of 16 k), v-inner (8): A-frags = split(y_v * x) built in
// regs from fp32 X smem; B staged in 16-k slices (48B pitch, conflict-free
// ldsm), double-buffered; X per-kc double-buffered (80B pitch: 16B-aligned).
// smem 48KB -> 2 CTAs/SM.
// ---------------------------------------------------------------------------
static const int FCTP_SMEM = 49152;  // ys 4K + xs 2x10240 + bh/bl 2x2x6144

template<bool COMBINE>
__global__ __launch_bounds__(256, 2)
void fctp_v(const float* __restrict__ X, const float* __restrict__ Y,
            const uint8_t* __restrict__ Bp,   // hi slot base; lo at +262144
            float* __restrict__ C, const float* __restrict__ SC,
            const float* __restrict__ ANG, int N)
{
    extern __shared__ uint8_t smraw[];
    float* ys = (float*)smraw;                       // [128][8]
    float* xs = (float*)(smraw + 4096);              // [2][128][20] fp32 (80B pitch)
    const uint32_t xs_a = smem_u32(xs);
    const uint32_t bh_a = smem_u32(smraw + 24576);   // [2][128][24] bf16
    const uint32_t bl_a = smem_u32(smraw + 36864);   // [2][128][24] bf16

    const int tid = threadIdx.x, wid = tid >> 5, lane = tid & 31;
    const int q = lane >> 2, t4 = lane & 3, grp = lane >> 3, rw = lane & 7;
    const int mw = (wid & 3) * 32, nw = (wid >> 2) * 64;
    const int r0 = blockIdx.x * 128;

    auto stageX = [&](int kc, int b) {
#pragma unroll
        for (int t = 0; t < 2; ++t) {
            int idx = tid + t * 256;
            int row = idx >> 2, seg = idx & 3;
            int r = r0 + row;
            const float* src = X + (size_t)((r < N) ? r : 0) * 128 + kc * 16 + seg * 4;
            cp16(xs_a + (uint32_t)(b * 10240 + row * 80 + seg * 16), src);
        }
    };
    auto stageB = [&](int v, int kc, int b) {
#pragma unroll
        for (int t = 0; t < 2; ++t) {
            int idx = tid + t * 256;
            int split = idx >> 8, r2 = idx & 255;
            int row = r2 >> 1, seg = r2 & 1;
            const uint8_t* src = Bp + (size_t)split * 262144 + (size_t)v * 32768
                               + row * 256 + kc * 32 + seg * 16;
            uint32_t dst = (split ? bl_a : bh_a) + (uint32_t)(b * 6144 + row * 48 + seg * 16);
            cp16(dst, src);
        }
    };

    stageX(0, 0);
    stageB(0, 0, 0);
    CP_COMMIT();

    // ys (plain stores; covered by first __syncthreads)
    for (int i = tid; i < 1024; i += 256) {
        int n = i >> 3, v = i & 7, r = r0 + n;
        ys[i] = (r < N) ? Y[(size_t)r * 8 + v] : 0.f;
    }

    float fin[2][8][4];
#pragma unroll
    for (int mg = 0; mg < 2; ++mg)
#pragma unroll
        for (int j = 0; j < 8; ++j)
#pragma unroll
            for (int i = 0; i < 4; ++i) fin[mg][j][i] = 0.f;

    for (int t = 0; t < 64; ++t) {
        const int kc = t >> 3, v = t & 7;
        CP_WAIT0();
        __syncthreads();
        if (t < 63) {
            int tn = t + 1;
            stageB(tn & 7, tn >> 3, tn & 1);
            if (v == 0 && kc < 7) stageX(kc + 1, (kc + 1) & 1);
            CP_COMMIT();
        }

        const float* xb = xs + (kc & 1) * 2560;     // 128*20 floats
        const uint32_t bhb = bh_a + (t & 1) * 6144;
        const uint32_t blb = bl_a + (t & 1) * 6144;

        // Build A-frags: split(y_v * x) at fragment positions
        uint32_t ah[2][4], al[2][4];
#pragma unroll
        for (int mg = 0; mg < 2; ++mg) {
            int rA = mw + 16 * mg + q, rB = rA + 8;
            float yva = ys[rA * 8 + v], yvb = ys[rB * 8 + v];
            float2 xa0 = *(const float2*)(xb + rA * 20 + 2 * t4);
            float2 xb0 = *(const float2*)(xb + rB * 20 + 2 * t4);
            float2 xa1 = *(const float2*)(xb + rA * 20 + 8 + 2 * t4);
            float2 xb1 = *(const float2*)(xb + rB * 20 + 8 + 2 * t4);
            float p0, p1;
            p0 = xa0.x * yva; p1 = xa0.y * yva;
            ah[mg][0] = pack_hi(p0, p1); al[mg][0] = pack_lo(p0, p1, ah[mg][0]);
            p0 = xb0.x * yvb; p1 = xb0.y * yvb;
            ah[mg][1] = pack_hi(p0, p1); al[mg][1] = pack_lo(p0, p1, ah[mg][1]);
            p0 = xa1.x * yva; p1 = xa1.y * yva;
            ah[mg][2] = pack_hi(p0, p1); al[mg][2] = pack_lo(p0, p1, ah[mg][2]);
            p0 = xb1.x * yvb; p1 = xb1.y * yvb;
            ah[mg][3] = pack_hi(p0, p1); al[mg][3] = pack_lo(p0, p1, ah[mg][3]);
        }

#pragma unroll
        for (int jj = 0; jj < 4; ++jj) {
            int nrow = nw + 8 * (2 * jj + (grp >> 1)) + rw;
            uint32_t off = (uint32_t)(nrow * 48 + ((grp & 1) * 8) * 2);
            uint32_t bhf[4], blf[4];
            ldsm4(bhf, bhb + off);
            ldsm4(blf, blb + off);
#pragma unroll
            for (int mg = 0; mg < 2; ++mg) {
                mma16816(fin[mg][2 * jj],     ah[mg], bhf);
                mma16816(fin[mg][2 * jj + 1], ah[mg], bhf + 2);
                mma16816(fin[mg][2 * jj],     al[mg], bhf);
                mma16816(fin[mg][2 * jj + 1], al[mg], bhf + 2);
                mma16816(fin[mg][2 * jj],     ah[mg], blf);
                mma16816(fin[mg][2 * jj + 1], ah[mg], blf + 2);
            }
        }
    }

    // epilogue
    const float sk = 0.03125f;   // 1/sqrt(128*8)
#pragma unroll
    for (int mg = 0; mg < 2; ++mg) {
#pragma unroll
        for (int h = 0; h < 2; ++h) {
            int m = r0 + mw + 16 * mg + 8 * h + q;
            if (m >= N) continue;
            float ca = 1.f, sa = 0.f;
            if (COMBINE) { float a = ANG[m]; ca = cosf(a); sa = sinf(a); }
#pragma unroll
            for (int j = 0; j < 8; ++j) {
                int col = nw + 8 * j + 2 * t4;
                float2 val = make_float2(fin[mg][j][2 * h] * sk, fin[mg][j][2 * h + 1] * sk);
                if (COMBINE) {
                    const float* sp = SC + (size_t)m * 128 + col;
                    val.x = ca * sp[0] + sa * val.x;
                    val.y = ca * sp[1] + sa * val.y;
                }
                *(float2*)(C + (size_t)m * 128 + col) = val;
            }
        }
    }
}

// ---------------------------------------------------------------------------
// Fused edge MLP + scatter (R8 proven version, unchanged)
// ---------------------------------------------------------------------------
static const int EDGE_SMEM = 106496;   // b1 hi/lo [128][72] + b2 hi/lo [128][136]

__global__ __launch_bounds__(512, 1)
void edge_mlp_mma(const float* __restrict__ ES,
                  const __nv_bfloat16* __restrict__ B1h, const __nv_bfloat16* __restrict__ B1l,
                  const __nv_bfloat16* __restrict__ B2h, const __nv_bfloat16* __restrict__ B2l,
                  const float* __restrict__ SF, const int* __restrict__ SRC,
                  const int* __restrict__ DST, const float* __restrict__ EA,
                  float* __restrict__ RF, int E)
{
    extern __shared__ __align__(16) __nv_bfloat16 sm[];
    __nv_bfloat16* b1h = sm;              // [128][72]
    __nv_bfloat16* b1l = sm + 9216;
    __nv_bfloat16* b2h = sm + 18432;      // [128][136]
    __nv_bfloat16* b2l = sm + 35840;

    const int tid = threadIdx.x, wid = tid >> 5, lane = tid & 31;
    const int e0 = blockIdx.x * 256;
    const int q = lane >> 2, t4 = lane & 3, grp = lane >> 3, rw = lane & 7;

    for (int i = tid; i < 1024; i += 512) {
        int n = i >> 3, seg = i & 7;
        *(uint4*)(b1h + n * 72 + seg * 8) = *(const uint4*)(B1h + (size_t)n * 64 + seg * 8);
        *(uint4*)(b1l + n * 72 + seg * 8) = *(const uint4*)(B1l + (size_t)n * 64 + seg * 8);
    }
    for (int i = tid; i < 2048; i += 512) {
        int n = i >> 4, seg = i & 15;
        *(uint4*)(b2h + n * 136 + seg * 8) = *(const uint4*)(B2h + (size_t)n * 128 + seg * 8);
        *(uint4*)(b2l + n * 136 + seg * 8) = *(const uint4*)(B2l + (size_t)n * 128 + seg * 8);
    }
    __syncthreads();

    const uint32_t s1h = smem_u32(b1h), s1l = smem_u32(b1l);
    const uint32_t s2h = smem_u32(b2h), s2l = smem_u32(b2l);

    const int r0e = e0 + wid * 16 + q, r1e = r0e + 8;
    const int ce0 = (r0e < E) ? r0e : 0, ce1 = (r1e < E) ? r1e : 0;
    const float* es0 = ES + (size_t)ce0 * 64;
    const float* es1 = ES + (size_t)ce1 * 64;

    float acc1[16][4];
#pragma unroll
    for (int j = 0; j < 16; ++j)
#pragma unroll
        for (int i = 0; i < 4; ++i) acc1[j][i] = 0.f;

    // GEMM1: [256x64] @ [64x128]; A from gmem
#pragma unroll
    for (int s = 0; s < 4; ++s) {
        float2 x0a = *(const float2*)(es0 + s * 16 + 2 * t4);
        float2 x0b = *(const float2*)(es1 + s * 16 + 2 * t4);
        float2 x1a = *(const float2*)(es0 + s * 16 + 8 + 2 * t4);
        float2 x1b = *(const float2*)(es1 + s * 16 + 8 + 2 * t4);
        uint32_t ah[4], al[4];
        ah[0] = pack_hi(x0a.x, x0a.y); al[0] = pack_lo(x0a.x, x0a.y, ah[0]);
        ah[1] = pack_hi(x0b.x, x0b.y); al[1] = pack_lo(x0b.x, x0b.y, ah[1]);
        ah[2] = pack_hi(x1a.x, x1a.y); al[2] = pack_lo(x1a.x, x1a.y, ah[2]);
        ah[3] = pack_hi(x1b.x, x1b.y); al[3] = pack_lo(x1b.x, x1b.y, ah[3]);
#pragma unroll
        for (int jj = 0; jj < 8; ++jj) {
            int nrow = 8 * (2 * jj + (grp >> 1)) + rw;
            int kc = s * 16 + (grp & 1) * 8;
            uint32_t off = (uint32_t)(nrow * 72 + kc) * 2;
            uint32_t bh[4], bl[4];
            ldsm4(bh, s1h + off);
            ldsm4(bl, s1l + off);
            mma16816(acc1[2 * jj],     ah, bh);
            mma16816(acc1[2 * jj + 1], ah, bh + 2);
            mma16816(acc1[2 * jj],     al, bh);
            mma16816(acc1[2 * jj + 1], al, bh + 2);
            mma16816(acc1[2 * jj],     ah, bl);
            mma16816(acc1[2 * jj + 1], ah, bl + 2);
        }
    }

    // silu + pack A2 fragments (frees acc1)
    uint32_t pah[8][4], pal[8][4];
#pragma unroll
    for (int s = 0; s < 8; ++s) {
        float h00 = silu_n(acc1[2 * s][0]     * 0.125f);
        float h01 = silu_n(acc1[2 * s][1]     * 0.125f);
        float h02 = silu_n(acc1[2 * s][2]     * 0.125f);
        float h03 = silu_n(acc1[2 * s][3]     * 0.125f);
        float h10 = silu_n(acc1[2 * s + 1][0] * 0.125f);
        float h11 = silu_n(acc1[2 * s + 1][1] * 0.125f);
        float h12 = silu_n(acc1[2 * s + 1][2] * 0.125f);
        float h13 = silu_n(acc1[2 * s + 1][3] * 0.125f);
        pah[s][0] = pack_hi(h00, h01); pal[s][0] = pack_lo(h00, h01, pah[s][0]);
        pah[s][1] = pack_hi(h02, h03); pal[s][1] = pack_lo(h02, h03, pah[s][1]);
        pah[s][2] = pack_hi(h10, h11); pal[s][2] = pack_lo(h10, h11, pah[s][2]);
        pah[s][3] = pack_hi(h12, h13); pal[s][3] = pack_lo(h12, h13, pah[s][3]);
    }

    // GEMM2 + fused scatter, two 64-column halves
    const float sk = 0.08838834764831845f;   // 1/sqrt(128)
#pragma unroll
    for (int half = 0; half < 2; ++half) {
        float acc2[8][4];
#pragma unroll
        for (int j = 0; j < 8; ++j)
#pragma unroll
            for (int i = 0; i < 4; ++i) acc2[j][i] = 0.f;

#pragma unroll
        for (int s = 0; s < 8; ++s) {
#pragma unroll
            for (int jj = 0; jj < 4; ++jj) {
                int nrow = half * 64 + 8 * (2 * jj + (grp >> 1)) + rw;
                int kc = s * 16 + (grp & 1) * 8;
                uint32_t off = (uint32_t)(nrow * 136 + kc) * 2;
                uint32_t bh[4], bl[4];
                ldsm4(bh, s2h + off);
                ldsm4(bl, s2l + off);
                mma16816(acc2[2 * jj],     pah[s], bh);
                mma16816(acc2[2 * jj + 1], pah[s], bh + 2);
                mma16816(acc2[2 * jj],     pal[s], bh);
                mma16816(acc2[2 * jj + 1], pal[s], bh + 2);
                mma16816(acc2[2 * jj],     pah[s], bl);
                mma16816(acc2[2 * jj + 1], pah[s], bl + 2);
            }
        }

#pragma unroll
        for (int h = 0; h < 2; ++h) {
            int er = h ? r1e : r0e;
            if (er >= E) continue;
            int sidx = SRC[er], didx = DST[er];
            float ea = EA[er] * 0.17677669529663687f * sk;
            const float* sfr = SF + (size_t)sidx * 128 + half * 64;
            float* rfr = RF + (size_t)didx * 128 + half * 64;
#pragma unroll
            for (int j = 0; j < 8; ++j) {
                int col = 8 * j + 2 * t4;
                float2 s2 = *(const float2*)(sfr + col);
                redv2(rfr + col, acc2[j][2 * h] * ea * s2.x, acc2[j][2 * h + 1] * ea * s2.y);
            }
        }
    }
}

// ---------------------------------------------------------------------------
// Angle: ang[n] = 0.1/32 * sum_{u,v} rf[n,u] rattr[n,v] W3[u*8+v]; warp/node
// ---------------------------------------------------------------------------
__global__ void angle_kernel(const float* __restrict__ RF, const float* __restrict__ RA,
                             const float* __restrict__ W3, float* __restrict__ ANG, int N)
{
    int gw   = (blockIdx.x * blockDim.x + threadIdx.x) >> 5;
    int lane = threadIdx.x & 31;
    if (gw >= N) return;
    float ya[8];
#pragma unroll
    for (int v = 0; v < 8; ++v) ya[v] = RA[(size_t)gw * 8 + v];
    float sacc = 0.f;
#pragma unroll
    for (int uu = 0; uu < 4; ++uu) {
        int u = lane + uu * 32;
        float xv = RF[(size_t)gw * 128 + u];
#pragma unroll
        for (int v = 0; v < 8; ++v) sacc += xv * ya[v] * W3[u * 8 + v];
    }
#pragma unroll
    for (int off = 16; off; off >>= 1) sacc += __shfl_xor_sync(0xffffffffu, sacc, off);
    if (lane == 0) ANG[gw] = 0.003125f * sacc;   // 0.1 / 32
}

// ---------------------------------------------------------------------------
extern "C" void kernel_launch(void* const* d_in, const int* in_sizes, int n_in,
                              void* d_out, int out_size)
{
    const float* sender_input   = (const float*)d_in[0];
    const float* sender_attr    = (const float*)d_in[1];
    const float* receiver_input = (const float*)d_in[2];
    const float* receiver_attr  = (const float*)d_in[3];
    const int*   edge_src       = (const int*)  d_in[4];
    const int*   edge_dst       = (const int*)  d_in[5];
    const float* edge_attr      = (const float*)d_in[6];
    const float* edge_scalars   = (const float*)d_in[7];
    const float* W_sc           = (const float*)d_in[8];
    const float* W_lin1         = (const float*)d_in[9];
    const float* W_fc1          = (const float*)d_in[10];
    const float* W_fc2          = (const float*)d_in[11];
    const float* W_lin2         = (const float*)d_in[12];
    const float* W_lin3         = (const float*)d_in[13];

    const int Ns = in_sizes[0] / 128;
    const int Nr = in_sizes[2] / 128;
    const int E  = in_sizes[4];

    float *sf_p, *sc_p, *rf_p, *ang_p;
    uint8_t* wp;
    cudaGetSymbolAddress((void**)&sf_p,  g_sf);
    cudaGetSymbolAddress((void**)&sc_p,  g_sc);
    cudaGetSymbolAddress((void**)&rf_p,  g_rf);
    cudaGetSymbolAddress((void**)&ang_p, g_ang);
    cudaGetSymbolAddress((void**)&wp,    g_wp);

    cudaFuncSetAttribute(edge_mlp_mma,  cudaFuncAttributeMaxDynamicSharedMemorySize, EDGE_SMEM);
    cudaFuncSetAttribute(fctp_v<false>, cudaFuncAttributeMaxDynamicSharedMemorySize, FCTP_SMEM);
    cudaFuncSetAttribute(fctp_v<true>,  cudaFuncAttributeMaxDynamicSharedMemorySize, FCTP_SMEM);

    // --- merged weight prep ---
    prep_all<<<816, 256>>>(W_fc1, W_fc2, W_lin1, W_sc, W_lin2, wp);

    cudaMemsetAsync(rf_p, 0, (size_t)Nr * 128 * sizeof(float));

    // --- sender features ---
    fctp_v<false><<<(Ns + 127) / 128, 256, FCTP_SMEM>>>(sender_input, sender_attr,
        wp + 4 * 262144, sf_p, nullptr, nullptr, Ns);

    // --- receiver self connection ---
    fctp_v<false><<<(Nr + 127) / 128, 256, FCTP_SMEM>>>(receiver_input, receiver_attr,
        wp + 6 * 262144, sc_p, nullptr, nullptr, Nr);

    // --- fused edge MLP + scatter ---
    edge_mlp_mma<<<(E + 255) / 256, 512, EDGE_SMEM>>>(
        edge_scalars,
        (const __nv_bfloat16*)wp, (const __nv_bfloat16*)(wp + 262144),
        (const __nv_bfloat16*)(wp + 2 * 262144), (const __nv_bfloat16*)(wp + 3 * 262144),
        sf_p, edge_src, edge_dst, edge_attr, rf_p, E);

    // --- angle + final fctp with gating epilogue ---
    angle_kernel<<<((long long)Nr * 32 + 255) / 256, 256>>>(rf_p, receiver_attr, W_lin3, ang_p, Nr);
    fctp_v<true><<<(Nr + 127) / 128, 256, FCTP_SMEM>>>(rf_p, receiver_attr,
        wp + 8 * 262144, (float*)d_out, sc_p, ang_p, Nr);
}

// round 11
// speedup vs baseline: 1.1219x; 1.1219x over previous
#include <cuda_runtime.h>
#include <cuda_bf16.h>
#include <math.h>
#include <stdint.h>

// ---------------------------------------------------------------------------
// Shapes: Ns=Nr=100000, E=600000, D=128, A=8, S=64, H=128
// ---------------------------------------------------------------------------
#define MAX_E 600000
#define MAX_N 100000

// Scratch (__device__ globals; allocation-free rule)
__device__ float g_sf [(size_t)MAX_N * 128];   // sender features
__device__ float g_sc [(size_t)MAX_N * 128];   // receiver self connection
__device__ float g_rf [(size_t)MAX_N * 128];   // scattered receiver features
__device__ float g_ang[(size_t)MAX_N];         // receiver angle
// Prepped weights, bf16; 256KB slots.
// slots 0/1: fc1 hi/lo  n-major [n][64]
// slots 2/3: fc2 hi/lo  n-major [n][128]
// slots 4/5: lin1 hi/lo v-major [v][n][k]  (8 x 128 x 128)
// slots 6/7: sc   hi/lo v-major
// slots 8/9: lin2 hi/lo v-major
__device__ __align__(1024) uint8_t g_wp[10][262144];

// ---------------------------------------------------------------------------
// mma.sync / ldmatrix / cp.async helpers (sm_80+/sm_90, no arch-a gating)
// ---------------------------------------------------------------------------
__device__ __forceinline__ uint32_t smem_u32(const void* p) {
    uint32_t a;
    asm("{ .reg .u64 t; cvta.to.shared.u64 t, %1; cvt.u32.u64 %0, t; }" : "=r"(a) : "l"(p));
    return a;
}

__device__ __forceinline__ void mma16816(float* d, const uint32_t* a, const uint32_t* b) {
    asm volatile(
        "mma.sync.aligned.m16n8k16.row.col.f32.bf16.bf16.f32 "
        "{%0,%1,%2,%3}, {%4,%5,%6,%7}, {%8,%9}, {%0,%1,%2,%3};"
        : "+f"(d[0]), "+f"(d[1]), "+f"(d[2]), "+f"(d[3])
        : "r"(a[0]), "r"(a[1]), "r"(a[2]), "r"(a[3]), "r"(b[0]), "r"(b[1]));
}

__device__ __forceinline__ void ldsm4(uint32_t* r, uint32_t addr) {
    asm volatile("ldmatrix.sync.aligned.m8n8.x4.shared.b16 {%0,%1,%2,%3}, [%4];"
                 : "=r"(r[0]), "=r"(r[1]), "=r"(r[2]), "=r"(r[3]) : "r"(addr));
}

__device__ __forceinline__ void cp16(uint32_t s, const void* g) {
    asm volatile("cp.async.cg.shared.global [%0], [%1], 16;"
                 :: "r"(s), "l"(g) : "memory");
}
#define CP_COMMIT() asm volatile("cp.async.commit_group;" ::: "memory")
#define CP_WAIT0()  asm volatile("cp.async.wait_group 0;" ::: "memory")

// vector float2 reduction (PTX 8.1, sm_90+)
__device__ __forceinline__ void redv2(float* addr, float a, float b) {
    asm volatile("red.global.add.v2.f32 [%0], {%1, %2};" :: "l"(addr), "f"(a), "f"(b) : "memory");
}

// pack two fp32 -> bf16x2 (hi), and residual (lo)
__device__ __forceinline__ uint32_t pack_hi(float a, float b) {
    __nv_bfloat162 h = __float22bfloat162_rn(make_float2(a, b));
    return *(uint32_t*)&h;
}
__device__ __forceinline__ uint32_t pack_lo(float a, float b, uint32_t hp) {
    __nv_bfloat162 h = *(__nv_bfloat162*)&hp;
    float2 hf = __bfloat1622float2(h);
    __nv_bfloat162 l = __float22bfloat162_rn(make_float2(a - hf.x, b - hf.y));
    return *(uint32_t*)&l;
}

__device__ __forceinline__ float silu_n(float x) {
    return 1.679177f * x / (1.f + expf(-x));
}

// ---------------------------------------------------------------------------
// Merged weight prep (ONE launch)
// ---------------------------------------------------------------------------
__global__ void prep_all(const float* __restrict__ Wfc1, const float* __restrict__ Wfc2,
                         const float* __restrict__ Wl1,  const float* __restrict__ Wsc,
                         const float* __restrict__ Wl2,  uint8_t* __restrict__ wp)
{
    int idx = blockIdx.x * blockDim.x + threadIdx.x;
    if (idx < 4096) {                    // fc1
        int n = idx >> 5, kp = (idx & 31) << 1;
        float a = Wfc1[(size_t)kp * 128 + n];
        float b = Wfc1[(size_t)(kp + 1) * 128 + n];
        uint32_t h = pack_hi(a, b), l = pack_lo(a, b, h);
        ((uint32_t*)(wp))[n * 32 + (kp >> 1)] = h;
        ((uint32_t*)(wp + 262144))[n * 32 + (kp >> 1)] = l;
    } else if (idx < 12288) {            // fc2
        int i = idx - 4096;
        int n = i >> 6, kp = (i & 63) << 1;
        float a = Wfc2[(size_t)kp * 128 + n];
        float b = Wfc2[(size_t)(kp + 1) * 128 + n];
        uint32_t h = pack_hi(a, b), l = pack_lo(a, b, h);
        ((uint32_t*)(wp + 2 * 262144))[n * 64 + (kp >> 1)] = h;
        ((uint32_t*)(wp + 3 * 262144))[n * 64 + (kp >> 1)] = l;
    } else if (idx < 208896) {           // lin weights, v-major
        int i = idx - 12288;
        int w = i >> 16;                 // 0=lin1 1=sc 2=lin2
        int r = i & 65535;
        int v = r >> 13, n = (r >> 6) & 127, up = r & 63, u = up << 1;
        const float* W = (w == 0) ? Wl1 : (w == 1) ? Wsc : Wl2;
        float a = W[(size_t)(u * 8 + v) * 128 + n];
        float b = W[(size_t)((u + 1) * 8 + v) * 128 + n];
        uint32_t h = pack_hi(a, b), l = pack_lo(a, b, h);
        ((uint32_t*)(wp + (size_t)(4 + 2 * w) * 262144))[v * 8192 + n * 64 + up] = h;
        ((uint32_t*)(wp + (size_t)(5 + 2 * w) * 262144))[v * 8192 + n * 64 + up] = l;
    }
}

// ---------------------------------------------------------------------------
// fctp (v-loop): out[m,w] = scale * sum_v Y[m,v] * (X @ W_v)[m,w]
// Tile: 128 nodes x 128 cols, 16 WARPS (512 thr), warp tile 32m x 32n.
// X split hi/lo ONCE into smem; per-v B double-buffered via cp.async
// (prefetch before MMA phase); per-v GEMM into tmp regs, fp32 Y-contraction.
// vs R8: 2x warps per SM (4/SMSP) with halved per-warp work -> hides latency.
// ---------------------------------------------------------------------------
static const int FCTP_SMEM = 212992;  // ys 4K + xh/xl 2x34816 + bh/bl 2x2x34816

template<bool COMBINE>
__global__ __launch_bounds__(512, 1)
void fctp_v(const float* __restrict__ X, const float* __restrict__ Y,
            const uint8_t* __restrict__ Bp,   // hi slot base; lo at +262144
            float* __restrict__ C, const float* __restrict__ SC,
            const float* __restrict__ ANG, int N)
{
    extern __shared__ uint8_t smraw[];
    float* ys = (float*)smraw;                                  // [128][8]
    __nv_bfloat16* xh = (__nv_bfloat16*)(smraw + 4096);         // [128][136]
    __nv_bfloat16* xl = xh + 17408;
    __nv_bfloat16* bh = xl + 17408;                             // [2][128][136]
    __nv_bfloat16* bl = bh + 34816;

    const int tid = threadIdx.x, wid = tid >> 5, lane = tid & 31;
    const int q = lane >> 2, t4 = lane & 3, grp = lane >> 3, rw = lane & 7;
    const int mw = (wid & 3) * 32, nwq = (wid >> 2) * 32;
    const int r0 = blockIdx.x * 128;
    const uint32_t xh_a = smem_u32(xh), xl_a = smem_u32(xl);
    const uint32_t bh_a = smem_u32(bh), bl_a = smem_u32(bl);

    auto stageB = [&](int v, int b) {
        const uint8_t* sh = Bp + (size_t)v * 32768;
        const uint8_t* sl = Bp + 262144 + (size_t)v * 32768;
#pragma unroll
        for (int t = 0; t < 4; ++t) {
            int idx = tid + t * 512;
            int n = idx >> 4, seg = idx & 15;
            uint32_t d = (uint32_t)(b * 34816 + n * 272 + seg * 16);
            cp16(bh_a + d, sh + n * 256 + seg * 16);
            cp16(bl_a + d, sl + n * 256 + seg * 16);
        }
    };

    stageB(0, 0); CP_COMMIT();

    // ys
    for (int i = tid; i < 1024; i += 512) {
        int n = i >> 3, v = i & 7, r = r0 + n;
        ys[i] = (r < N) ? Y[(size_t)r * 8 + v] : 0.f;
    }

    // X split hi/lo into smem (once per tile; plain stores, synced in loop)
    {
        int m = tid >> 2, quarter = tid & 3, r = r0 + m;
        const float* xr = X + (size_t)r * 128 + quarter * 32;
#pragma unroll
        for (int g = 0; g < 4; ++g) {
            float4 f0 = make_float4(0.f, 0.f, 0.f, 0.f), f1 = f0;
            if (r < N) {
                f0 = *(const float4*)(xr + g * 8);
                f1 = *(const float4*)(xr + g * 8 + 4);
            }
            uint32_t h[4], l[4];
            h[0] = pack_hi(f0.x, f0.y); l[0] = pack_lo(f0.x, f0.y, h[0]);
            h[1] = pack_hi(f0.z, f0.w); l[1] = pack_lo(f0.z, f0.w, h[1]);
            h[2] = pack_hi(f1.x, f1.y); l[2] = pack_lo(f1.x, f1.y, h[2]);
            h[3] = pack_hi(f1.z, f1.w); l[3] = pack_lo(f1.z, f1.w, h[3]);
            int eo = m * 136 + quarter * 32 + g * 8;
            *(uint4*)(xh + eo) = make_uint4(h[0], h[1], h[2], h[3]);
            *(uint4*)(xl + eo) = make_uint4(l[0], l[1], l[2], l[3]);
        }
    }

    float fin[2][4][4];
#pragma unroll
    for (int mg = 0; mg < 2; ++mg)
#pragma unroll
        for (int j = 0; j < 4; ++j)
#pragma unroll
            for (int i = 0; i < 4; ++i) fin[mg][j][i] = 0.f;

    for (int v = 0; v < 8; ++v) {
        CP_WAIT0();
        __syncthreads();
        if (v < 7) { stageB(v + 1, (v + 1) & 1); CP_COMMIT(); }

        const int b = v & 1;
        float tmp[2][4][4];
#pragma unroll
        for (int mg = 0; mg < 2; ++mg)
#pragma unroll
            for (int j = 0; j < 4; ++j)
#pragma unroll
                for (int i = 0; i < 4; ++i) tmp[mg][j][i] = 0.f;

#pragma unroll
        for (int kc = 0; kc < 8; ++kc) {
            uint32_t ah[2][4], al[2][4];
#pragma unroll
            for (int mg = 0; mg < 2; ++mg) {
                uint32_t ao = (uint32_t)((mw + 16 * mg + rw + (grp & 1) * 8) * 272
                                         + (kc * 16 + (grp >> 1) * 8) * 2);
                ldsm4(ah[mg], xh_a + ao);
                ldsm4(al[mg], xl_a + ao);
            }
#pragma unroll
            for (int jj = 0; jj < 2; ++jj) {
                int nrow = nwq + 8 * (2 * jj + (grp >> 1)) + rw;
                int kcol = kc * 16 + (grp & 1) * 8;
                uint32_t off = (uint32_t)(b * 34816 + nrow * 272 + kcol * 2);
                uint32_t bhf[4], blf[4];
                ldsm4(bhf, bh_a + off);
                ldsm4(blf, bl_a + off);
#pragma unroll
                for (int mg = 0; mg < 2; ++mg) {
                    mma16816(tmp[mg][2 * jj],     ah[mg], bhf);
                    mma16816(tmp[mg][2 * jj + 1], ah[mg], bhf + 2);
                    mma16816(tmp[mg][2 * jj],     al[mg], bhf);
                    mma16816(tmp[mg][2 * jj + 1], al[mg], bhf + 2);
                    mma16816(tmp[mg][2 * jj],     ah[mg], blf);
                    mma16816(tmp[mg][2 * jj + 1], ah[mg], blf + 2);
                }
            }
        }

        // fp32 Y-contraction (no extra rounding)
#pragma unroll
        for (int mg = 0; mg < 2; ++mg) {
            float yva = ys[(mw + 16 * mg + q) * 8 + v];
            float yvb = ys[(mw + 16 * mg + q + 8) * 8 + v];
#pragma unroll
            for (int j = 0; j < 4; ++j) {
                fin[mg][j][0] += yva * tmp[mg][j][0];
                fin[mg][j][1] += yva * tmp[mg][j][1];
                fin[mg][j][2] += yvb * tmp[mg][j][2];
                fin[mg][j][3] += yvb * tmp[mg][j][3];
            }
        }
    }

    // epilogue
    const float sk = 0.03125f;   // 1/sqrt(128*8)
#pragma unroll
    for (int mg = 0; mg < 2; ++mg) {
#pragma unroll
        for (int h = 0; h < 2; ++h) {
            int m = r0 + mw + 16 * mg + 8 * h + q;
            if (m >= N) continue;
            float ca = 1.f, sa = 0.f;
            if (COMBINE) { float a = ANG[m]; ca = cosf(a); sa = sinf(a); }
#pragma unroll
            for (int j = 0; j < 4; ++j) {
                int col = nwq + 8 * j + 2 * t4;
                float2 val = make_float2(fin[mg][j][2 * h] * sk, fin[mg][j][2 * h + 1] * sk);
                if (COMBINE) {
                    const float* sp = SC + (size_t)m * 128 + col;
                    val.x = ca * sp[0] + sa * val.x;
                    val.y = ca * sp[1] + sa * val.y;
                }
                *(float2*)(C + (size_t)m * 128 + col) = val;
            }
        }
    }
}

// ---------------------------------------------------------------------------
// Fused edge MLP + scatter (R8 proven version, unchanged)
// ---------------------------------------------------------------------------
static const int EDGE_SMEM = 106496;   // b1 hi/lo [128][72] + b2 hi/lo [128][136]

__global__ __launch_bounds__(512, 1)
void edge_mlp_mma(const float* __restrict__ ES,
                  const __nv_bfloat16* __restrict__ B1h, const __nv_bfloat16* __restrict__ B1l,
                  const __nv_bfloat16* __restrict__ B2h, const __nv_bfloat16* __restrict__ B2l,
                  const float* __restrict__ SF, const int* __restrict__ SRC,
                  const int* __restrict__ DST, const float* __restrict__ EA,
                  float* __restrict__ RF, int E)
{
    extern __shared__ __align__(16) __nv_bfloat16 sm[];
    __nv_bfloat16* b1h = sm;              // [128][72]
    __nv_bfloat16* b1l = sm + 9216;
    __nv_bfloat16* b2h = sm + 18432;      // [128][136]
    __nv_bfloat16* b2l = sm + 35840;

    const int tid = threadIdx.x, wid = tid >> 5, lane = tid & 31;
    const int e0 = blockIdx.x * 256;
    const int q = lane >> 2, t4 = lane & 3, grp = lane >> 3, rw = lane & 7;

    for (int i = tid; i < 1024; i += 512) {
        int n = i >> 3, seg = i & 7;
        *(uint4*)(b1h + n * 72 + seg * 8) = *(const uint4*)(B1h + (size_t)n * 64 + seg * 8);
        *(uint4*)(b1l + n * 72 + seg * 8) = *(const uint4*)(B1l + (size_t)n * 64 + seg * 8);
    }
    for (int i = tid; i < 2048; i += 512) {
        int n = i >> 4, seg = i & 15;
        *(uint4*)(b2h + n * 136 + seg * 8) = *(const uint4*)(B2h + (size_t)n * 128 + seg * 8);
        *(uint4*)(b2l + n * 136 + seg * 8) = *(const uint4*)(B2l + (size_t)n * 128 + seg * 8);
    }
    __syncthreads();

    const uint32_t s1h = smem_u32(b1h), s1l = smem_u32(b1l);
    const uint32_t s2h = smem_u32(b2h), s2l = smem_u32(b2l);

    const int r0e = e0 + wid * 16 + q, r1e = r0e + 8;
    const int ce0 = (r0e < E) ? r0e : 0, ce1 = (r1e < E) ? r1e : 0;
    const float* es0 = ES + (size_t)ce0 * 64;
    const float* es1 = ES + (size_t)ce1 * 64;

    float acc1[16][4];
#pragma unroll
    for (int j = 0; j < 16; ++j)
#pragma unroll
        for (int i = 0; i < 4; ++i) acc1[j][i] = 0.f;

    // GEMM1: [256x64] @ [64x128]; A from gmem
#pragma unroll
    for (int s = 0; s < 4; ++s) {
        float2 x0a = *(const float2*)(es0 + s * 16 + 2 * t4);
        float2 x0b = *(const float2*)(es1 + s * 16 + 2 * t4);
        float2 x1a = *(const float2*)(es0 + s * 16 + 8 + 2 * t4);
        float2 x1b = *(const float2*)(es1 + s * 16 + 8 + 2 * t4);
        uint32_t ah[4], al[4];
        ah[0] = pack_hi(x0a.x, x0a.y); al[0] = pack_lo(x0a.x, x0a.y, ah[0]);
        ah[1] = pack_hi(x0b.x, x0b.y); al[1] = pack_lo(x0b.x, x0b.y, ah[1]);
        ah[2] = pack_hi(x1a.x, x1a.y); al[2] = pack_lo(x1a.x, x1a.y, ah[2]);
        ah[3] = pack_hi(x1b.x, x1b.y); al[3] = pack_lo(x1b.x, x1b.y, ah[3]);
#pragma unroll
        for (int jj = 0; jj < 8; ++jj) {
            int nrow = 8 * (2 * jj + (grp >> 1)) + rw;
            int kc = s * 16 + (grp & 1) * 8;
            uint32_t off = (uint32_t)(nrow * 72 + kc) * 2;
            uint32_t bh[4], bl[4];
            ldsm4(bh, s1h + off);
            ldsm4(bl, s1l + off);
            mma16816(acc1[2 * jj],     ah, bh);
            mma16816(acc1[2 * jj + 1], ah, bh + 2);
            mma16816(acc1[2 * jj],     al, bh);
            mma16816(acc1[2 * jj + 1], al, bh + 2);
            mma16816(acc1[2 * jj],     ah, bl);
            mma16816(acc1[2 * jj + 1], ah, bl + 2);
        }
    }

    // silu + pack A2 fragments (frees acc1)
    uint32_t pah[8][4], pal[8][4];
#pragma unroll
    for (int s = 0; s < 8; ++s) {
        float h00 = silu_n(acc1[2 * s][0]     * 0.125f);
        float h01 = silu_n(acc1[2 * s][1]     * 0.125f);
        float h02 = silu_n(acc1[2 * s][2]     * 0.125f);
        float h03 = silu_n(acc1[2 * s][3]     * 0.125f);
        float h10 = silu_n(acc1[2 * s + 1][0] * 0.125f);
        float h11 = silu_n(acc1[2 * s + 1][1] * 0.125f);
        float h12 = silu_n(acc1[2 * s + 1][2] * 0.125f);
        float h13 = silu_n(acc1[2 * s + 1][3] * 0.125f);
        pah[s][0] = pack_hi(h00, h01); pal[s][0] = pack_lo(h00, h01, pah[s][0]);
        pah[s][1] = pack_hi(h02, h03); pal[s][1] = pack_lo(h02, h03, pah[s][1]);
        pah[s][2] = pack_hi(h10, h11); pal[s][2] = pack_lo(h10, h11, pah[s][2]);
        pah[s][3] = pack_hi(h12, h13); pal[s][3] = pack_lo(h12, h13, pah[s][3]);
    }

    // GEMM2 + fused scatter, two 64-column halves
    const float sk = 0.08838834764831845f;   // 1/sqrt(128)
#pragma unroll
    for (int half = 0; half < 2; ++half) {
        float acc2[8][4];
#pragma unroll
        for (int j = 0; j < 8; ++j)
#pragma unroll
            for (int i = 0; i < 4; ++i) acc2[j][i] = 0.f;

#pragma unroll
        for (int s = 0; s < 8; ++s) {
#pragma unroll
            for (int jj = 0; jj < 4; ++jj) {
                int nrow = half * 64 + 8 * (2 * jj + (grp >> 1)) + rw;
                int kc = s * 16 + (grp & 1) * 8;
                uint32_t off = (uint32_t)(nrow * 136 + kc) * 2;
                uint32_t bh[4], bl[4];
                ldsm4(bh, s2h + off);
                ldsm4(bl, s2l + off);
                mma16816(acc2[2 * jj],     pah[s], bh);
                mma16816(acc2[2 * jj + 1], pah[s], bh + 2);
                mma16816(acc2[2 * jj],     pal[s], bh);
                mma16816(acc2[2 * jj + 1], pal[s], bh + 2);
                mma16816(acc2[2 * jj],     pah[s], bl);
                mma16816(acc2[2 * jj + 1], pah[s], bl + 2);
            }
        }

#pragma unroll
        for (int h = 0; h < 2; ++h) {
            int er = h ? r1e : r0e;
            if (er >= E) continue;
            int sidx = SRC[er], didx = DST[er];
            float ea = EA[er] * 0.17677669529663687f * sk;
            const float* sfr = SF + (size_t)sidx * 128 + half * 64;
            float* rfr = RF + (size_t)didx * 128 + half * 64;
#pragma unroll
            for (int j = 0; j < 8; ++j) {
                int col = 8 * j + 2 * t4;
                float2 s2 = *(const float2*)(sfr + col);
                redv2(rfr + col, acc2[j][2 * h] * ea * s2.x, acc2[j][2 * h + 1] * ea * s2.y);
            }
        }
    }
}

// ---------------------------------------------------------------------------
// Angle: ang[n] = 0.1/32 * sum_{u,v} rf[n,u] rattr[n,v] W3[u*8+v]; warp/node
// ---------------------------------------------------------------------------
__global__ void angle_kernel(const float* __restrict__ RF, const float* __restrict__ RA,
                             const float* __restrict__ W3, float* __restrict__ ANG, int N)
{
    int gw   = (blockIdx.x * blockDim.x + threadIdx.x) >> 5;
    int lane = threadIdx.x & 31;
    if (gw >= N) return;
    float ya[8];
#pragma unroll
    for (int v = 0; v < 8; ++v) ya[v] = RA[(size_t)gw * 8 + v];
    float sacc = 0.f;
#pragma unroll
    for (int uu = 0; uu < 4; ++uu) {
        int u = lane + uu * 32;
        float xv = RF[(size_t)gw * 128 + u];
#pragma unroll
        for (int v = 0; v < 8; ++v) sacc += xv * ya[v] * W3[u * 8 + v];
    }
#pragma unroll
    for (int off = 16; off; off >>= 1) sacc += __shfl_xor_sync(0xffffffffu, sacc, off);
    if (lane == 0) ANG[gw] = 0.003125f * sacc;   // 0.1 / 32
}

// ---------------------------------------------------------------------------
extern "C" void kernel_launch(void* const* d_in, const int* in_sizes, int n_in,
                              void* d_out, int out_size)
{
    const float* sender_input   = (const float*)d_in[0];
    const float* sender_attr    = (const float*)d_in[1];
    const float* receiver_input = (const float*)d_in[2];
    const float* receiver_attr  = (const float*)d_in[3];
    const int*   edge_src       = (const int*)  d_in[4];
    const int*   edge_dst       = (const int*)  d_in[5];
    const float* edge_attr      = (const float*)d_in[6];
    const float* edge_scalars   = (const float*)d_in[7];
    const float* W_sc           = (const float*)d_in[8];
    const float* W_lin1         = (const float*)d_in[9];
    const float* W_fc1          = (const float*)d_in[10];
    const float* W_fc2          = (const float*)d_in[11];
    const float* W_lin2         = (const float*)d_in[12];
    const float* W_lin3         = (const float*)d_in[13];

    const int Ns = in_sizes[0] / 128;
    const int Nr = in_sizes[2] / 128;
    const int E  = in_sizes[4];

    float *sf_p, *sc_p, *rf_p, *ang_p;
    uint8_t* wp;
    cudaGetSymbolAddress((void**)&sf_p,  g_sf);
    cudaGetSymbolAddress((void**)&sc_p,  g_sc);
    cudaGetSymbolAddress((void**)&rf_p,  g_rf);
    cudaGetSymbolAddress((void**)&ang_p, g_ang);
    cudaGetSymbolAddress((void**)&wp,    g_wp);

    cudaFuncSetAttribute(edge_mlp_mma,  cudaFuncAttributeMaxDynamicSharedMemorySize, EDGE_SMEM);
    cudaFuncSetAttribute(fctp_v<false>, cudaFuncAttributeMaxDynamicSharedMemorySize, FCTP_SMEM);
    cudaFuncSetAttribute(fctp_v<true>,  cudaFuncAttributeMaxDynamicSharedMemorySize, FCTP_SMEM);

    // --- merged weight prep ---
    prep_all<<<816, 256>>>(W_fc1, W_fc2, W_lin1, W_sc, W_lin2, wp);

    cudaMemsetAsync(rf_p, 0, (size_t)Nr * 128 * sizeof(float));

    // --- sender features ---
    fctp_v<false><<<(Ns + 127) / 128, 512, FCTP_SMEM>>>(sender_input, sender_attr,
        wp + 4 * 262144, sf_p, nullptr, nullptr, Ns);

    // --- receiver self connection ---
    fctp_v<false><<<(Nr + 127) / 128, 512, FCTP_SMEM>>>(receiver_input, receiver_attr,
        wp + 6 * 262144, sc_p, nullptr, nullptr, Nr);

    // --- fused edge MLP + scatter ---
    edge_mlp_mma<<<(E + 255) / 256, 512, EDGE_SMEM>>>(
        edge_scalars,
        (const __nv_bfloat16*)wp, (const __nv_bfloat16*)(wp + 262144),
        (const __nv_bfloat16*)(wp + 2 * 262144), (const __nv_bfloat16*)(wp + 3 * 262144),
        sf_p, edge_src, edge_dst, edge_attr, rf_p, E);

    // --- angle + final fctp with gating epilogue ---
    angle_kernel<<<((long long)Nr * 32 + 255) / 256, 256>>>(rf_p, receiver_attr, W_lin3, ang_p, Nr);
    fctp_v<true><<<(Nr + 127) / 128, 512, FCTP_SMEM>>>(rf_p, receiver_attr,
        wp + 8 * 262144, (float*)d_out, sc_p, ang_p, Nr);
}

// round 12
// speedup vs baseline: 1.1261x; 1.0037x over previous
#include <cuda_runtime.h>
#include <cuda_bf16.h>
#include <math.h>
#include <stdint.h>

// ---------------------------------------------------------------------------
// Shapes: Ns=Nr=100000, E=600000, D=128, A=8, S=64, H=128
// ---------------------------------------------------------------------------
#define MAX_E 600000
#define MAX_N 100000

// Scratch (__device__ globals; allocation-free rule)
__device__ float g_sf [(size_t)MAX_N * 128];   // sender features
__device__ float g_sc [(size_t)MAX_N * 128];   // receiver self connection
__device__ float g_rf [(size_t)MAX_N * 128];   // scattered receiver features
// Prepped weights, bf16; 256KB slots.
// slots 0/1: fc1 hi/lo  n-major [n][64]
// slots 2/3: fc2 hi/lo  n-major [n][128]
// slots 4/5: lin1 hi/lo v-major [v][n][k]  (8 x 128 x 128)
// slots 6/7: sc   hi/lo v-major
// slots 8/9: lin2 hi/lo v-major
__device__ __align__(1024) uint8_t g_wp[10][262144];

// ---------------------------------------------------------------------------
// mma.sync / ldmatrix / cp.async helpers (sm_80+/sm_90, no arch-a gating)
// ---------------------------------------------------------------------------
__device__ __forceinline__ uint32_t smem_u32(const void* p) {
    uint32_t a;
    asm("{ .reg .u64 t; cvta.to.shared.u64 t, %1; cvt.u32.u64 %0, t; }" : "=r"(a) : "l"(p));
    return a;
}

__device__ __forceinline__ void mma16816(float* d, const uint32_t* a, const uint32_t* b) {
    asm volatile(
        "mma.sync.aligned.m16n8k16.row.col.f32.bf16.bf16.f32 "
        "{%0,%1,%2,%3}, {%4,%5,%6,%7}, {%8,%9}, {%0,%1,%2,%3};"
        : "+f"(d[0]), "+f"(d[1]), "+f"(d[2]), "+f"(d[3])
        : "r"(a[0]), "r"(a[1]), "r"(a[2]), "r"(a[3]), "r"(b[0]), "r"(b[1]));
}

__device__ __forceinline__ void ldsm4(uint32_t* r, uint32_t addr) {
    asm volatile("ldmatrix.sync.aligned.m8n8.x4.shared.b16 {%0,%1,%2,%3}, [%4];"
                 : "=r"(r[0]), "=r"(r[1]), "=r"(r[2]), "=r"(r[3]) : "r"(addr));
}

__device__ __forceinline__ void cp16(uint32_t s, const void* g) {
    asm volatile("cp.async.cg.shared.global [%0], [%1], 16;"
                 :: "r"(s), "l"(g) : "memory");
}
#define CP_COMMIT() asm volatile("cp.async.commit_group;" ::: "memory")
#define CP_WAIT0()  asm volatile("cp.async.wait_group 0;" ::: "memory")

// vector float2 reduction (PTX 8.1, sm_90+)
__device__ __forceinline__ void redv2(float* addr, float a, float b) {
    asm volatile("red.global.add.v2.f32 [%0], {%1, %2};" :: "l"(addr), "f"(a), "f"(b) : "memory");
}

// pack two fp32 -> bf16x2 (hi), and residual (lo)
__device__ __forceinline__ uint32_t pack_hi(float a, float b) {
    __nv_bfloat162 h = __float22bfloat162_rn(make_float2(a, b));
    return *(uint32_t*)&h;
}
__device__ __forceinline__ uint32_t pack_lo(float a, float b, uint32_t hp) {
    __nv_bfloat162 h = *(__nv_bfloat162*)&hp;
    float2 hf = __bfloat1622float2(h);
    __nv_bfloat162 l = __float22bfloat162_rn(make_float2(a - hf.x, b - hf.y));
    return *(uint32_t*)&l;
}

__device__ __forceinline__ float silu_n(float x) {
    return 1.679177f * x / (1.f + expf(-x));
}

// ---------------------------------------------------------------------------
// Merged weight prep (ONE launch)
// ---------------------------------------------------------------------------
__global__ void prep_all(const float* __restrict__ Wfc1, const float* __restrict__ Wfc2,
                         const float* __restrict__ Wl1,  const float* __restrict__ Wsc,
                         const float* __restrict__ Wl2,  uint8_t* __restrict__ wp)
{
    int idx = blockIdx.x * blockDim.x + threadIdx.x;
    if (idx < 4096) {                    // fc1
        int n = idx >> 5, kp = (idx & 31) << 1;
        float a = Wfc1[(size_t)kp * 128 + n];
        float b = Wfc1[(size_t)(kp + 1) * 128 + n];
        uint32_t h = pack_hi(a, b), l = pack_lo(a, b, h);
        ((uint32_t*)(wp))[n * 32 + (kp >> 1)] = h;
        ((uint32_t*)(wp + 262144))[n * 32 + (kp >> 1)] = l;
    } else if (idx < 12288) {            // fc2
        int i = idx - 4096;
        int n = i >> 6, kp = (i & 63) << 1;
        float a = Wfc2[(size_t)kp * 128 + n];
        float b = Wfc2[(size_t)(kp + 1) * 128 + n];
        uint32_t h = pack_hi(a, b), l = pack_lo(a, b, h);
        ((uint32_t*)(wp + 2 * 262144))[n * 64 + (kp >> 1)] = h;
        ((uint32_t*)(wp + 3 * 262144))[n * 64 + (kp >> 1)] = l;
    } else if (idx < 208896) {           // lin weights, v-major
        int i = idx - 12288;
        int w = i >> 16;                 // 0=lin1 1=sc 2=lin2
        int r = i & 65535;
        int v = r >> 13, n = (r >> 6) & 127, up = r & 63, u = up << 1;
        const float* W = (w == 0) ? Wl1 : (w == 1) ? Wsc : Wl2;
        float a = W[(size_t)(u * 8 + v) * 128 + n];
        float b = W[(size_t)((u + 1) * 8 + v) * 128 + n];
        uint32_t h = pack_hi(a, b), l = pack_lo(a, b, h);
        ((uint32_t*)(wp + (size_t)(4 + 2 * w) * 262144))[v * 8192 + n * 64 + up] = h;
        ((uint32_t*)(wp + (size_t)(5 + 2 * w) * 262144))[v * 8192 + n * 64 + up] = l;
    }
}

// ---------------------------------------------------------------------------
// fctp body (R11-proven): out[m,w] = scale * sum_v Y[m,v] * (X @ W_v)[m,w]
// Tile: 128 nodes x 128 cols, 16 warps, warp tile 32m x 32n.
// COMBINE: angle computed in-block from X(=rf), Y(=ra), W3 -> smem;
//          out = cos(ang)*SC + sin(ang)*scale*acc.
// ---------------------------------------------------------------------------
static const int FCTP_SMEM = 213504;  // ys 4K + xh/xl 2x34816 + bh/bl 2x2x34816 + ang 512

template<bool COMBINE>
__device__ __forceinline__ void fctp_body(
    int tileIdx, uint8_t* smraw,
    const float* __restrict__ X, const float* __restrict__ Y,
    const uint8_t* __restrict__ Bp,   // hi slot base; lo at +262144
    float* __restrict__ C, const float* __restrict__ SC,
    const float* __restrict__ W3, int N)
{
    float* ys = (float*)smraw;                                  // [128][8]
    __nv_bfloat16* xh = (__nv_bfloat16*)(smraw + 4096);         // [128][136]
    __nv_bfloat16* xl = xh + 17408;
    __nv_bfloat16* bh = xl + 17408;                             // [2][128][136]
    __nv_bfloat16* bl = bh + 34816;
    float* angs = (float*)(smraw + 212992);                     // [128]

    const int tid = threadIdx.x, wid = tid >> 5, lane = tid & 31;
    const int q = lane >> 2, t4 = lane & 3, grp = lane >> 3, rw = lane & 7;
    const int mw = (wid & 3) * 32, nwq = (wid >> 2) * 32;
    const int r0 = tileIdx * 128;
    const uint32_t xh_a = smem_u32(xh), xl_a = smem_u32(xl);
    const uint32_t bh_a = smem_u32(bh), bl_a = smem_u32(bl);

    auto stageB = [&](int v, int b) {
        const uint8_t* sh = Bp + (size_t)v * 32768;
        const uint8_t* sl = Bp + 262144 + (size_t)v * 32768;
#pragma unroll
        for (int t = 0; t < 4; ++t) {
            int idx = tid + t * 512;
            int n = idx >> 4, seg = idx & 15;
            uint32_t d = (uint32_t)(b * 34816 + n * 272 + seg * 16);
            cp16(bh_a + d, sh + n * 256 + seg * 16);
            cp16(bl_a + d, sl + n * 256 + seg * 16);
        }
    };

    stageB(0, 0); CP_COMMIT();

    // ys
    for (int i = tid; i < 1024; i += 512) {
        int n = i >> 3, v = i & 7, r = r0 + n;
        ys[i] = (r < N) ? Y[(size_t)r * 8 + v] : 0.f;
    }

    // fused angle (COMBINE only): ang[m] = 0.1/32 * sum_{u,v} X[m,u] Y[m,v] W3[u*8+v]
    if (COMBINE) {
        int node = tid >> 2, part = tid & 3;
        int m = r0 + node;
        float s = 0.f;
        if (m < N) {
            const float* xr = X + (size_t)m * 128 + part * 32;
            float ya[8];
#pragma unroll
            for (int v = 0; v < 8; ++v) ya[v] = Y[(size_t)m * 8 + v];
#pragma unroll
            for (int u = 0; u < 32; ++u) {
                float w = 0.f;
#pragma unroll
                for (int v = 0; v < 8; ++v) w += ya[v] * W3[(part * 32 + u) * 8 + v];
                s += xr[u] * w;
            }
        }
        s += __shfl_down_sync(0xffffffffu, s, 1);
        s += __shfl_down_sync(0xffffffffu, s, 2);
        if (part == 0) angs[node] = 0.003125f * s;   // 0.1/32
    }

    // X split hi/lo into smem (once per tile; plain stores, synced in loop)
    {
        int m = tid >> 2, quarter = tid & 3, r = r0 + m;
        const float* xr = X + (size_t)r * 128 + quarter * 32;
#pragma unroll
        for (int g = 0; g < 4; ++g) {
            float4 f0 = make_float4(0.f, 0.f, 0.f, 0.f), f1 = f0;
            if (r < N) {
                f0 = *(const float4*)(xr + g * 8);
                f1 = *(const float4*)(xr + g * 8 + 4);
            }
            uint32_t h[4], l[4];
            h[0] = pack_hi(f0.x, f0.y); l[0] = pack_lo(f0.x, f0.y, h[0]);
            h[1] = pack_hi(f0.z, f0.w); l[1] = pack_lo(f0.z, f0.w, h[1]);
            h[2] = pack_hi(f1.x, f1.y); l[2] = pack_lo(f1.x, f1.y, h[2]);
            h[3] = pack_hi(f1.z, f1.w); l[3] = pack_lo(f1.z, f1.w, h[3]);
            int eo = m * 136 + quarter * 32 + g * 8;
            *(uint4*)(xh + eo) = make_uint4(h[0], h[1], h[2], h[3]);
            *(uint4*)(xl + eo) = make_uint4(l[0], l[1], l[2], l[3]);
        }
    }

    float fin[2][4][4];
#pragma unroll
    for (int mg = 0; mg < 2; ++mg)
#pragma unroll
        for (int j = 0; j < 4; ++j)
#pragma unroll
            for (int i = 0; i < 4; ++i) fin[mg][j][i] = 0.f;

    for (int v = 0; v < 8; ++v) {
        CP_WAIT0();
        __syncthreads();
        if (v < 7) { stageB(v + 1, (v + 1) & 1); CP_COMMIT(); }

        const int b = v & 1;
        float tmp[2][4][4];
#pragma unroll
        for (int mg = 0; mg < 2; ++mg)
#pragma unroll
            for (int j = 0; j < 4; ++j)
#pragma unroll
                for (int i = 0; i < 4; ++i) tmp[mg][j][i] = 0.f;

#pragma unroll
        for (int kc = 0; kc < 8; ++kc) {
            uint32_t ah[2][4], al[2][4];
#pragma unroll
            for (int mg = 0; mg < 2; ++mg) {
                uint32_t ao = (uint32_t)((mw + 16 * mg + rw + (grp & 1) * 8) * 272
                                         + (kc * 16 + (grp >> 1) * 8) * 2);
                ldsm4(ah[mg], xh_a + ao);
                ldsm4(al[mg], xl_a + ao);
            }
#pragma unroll
            for (int jj = 0; jj < 2; ++jj) {
                int nrow = nwq + 8 * (2 * jj + (grp >> 1)) + rw;
                int kcol = kc * 16 + (grp & 1) * 8;
                uint32_t off = (uint32_t)(b * 34816 + nrow * 272 + kcol * 2);
                uint32_t bhf[4], blf[4];
                ldsm4(bhf, bh_a + off);
                ldsm4(blf, bl_a + off);
#pragma unroll
                for (int mg = 0; mg < 2; ++mg) {
                    mma16816(tmp[mg][2 * jj],     ah[mg], bhf);
                    mma16816(tmp[mg][2 * jj + 1], ah[mg], bhf + 2);
                    mma16816(tmp[mg][2 * jj],     al[mg], bhf);
                    mma16816(tmp[mg][2 * jj + 1], al[mg], bhf + 2);
                    mma16816(tmp[mg][2 * jj],     ah[mg], blf);
                    mma16816(tmp[mg][2 * jj + 1], ah[mg], blf + 2);
                }
            }
        }

        // fp32 Y-contraction (no extra rounding)
#pragma unroll
        for (int mg = 0; mg < 2; ++mg) {
            float yva = ys[(mw + 16 * mg + q) * 8 + v];
            float yvb = ys[(mw + 16 * mg + q + 8) * 8 + v];
#pragma unroll
            for (int j = 0; j < 4; ++j) {
                fin[mg][j][0] += yva * tmp[mg][j][0];
                fin[mg][j][1] += yva * tmp[mg][j][1];
                fin[mg][j][2] += yvb * tmp[mg][j][2];
                fin[mg][j][3] += yvb * tmp[mg][j][3];
            }
        }
    }

    // epilogue
    const float sk = 0.03125f;   // 1/sqrt(128*8)
#pragma unroll
    for (int mg = 0; mg < 2; ++mg) {
#pragma unroll
        for (int h = 0; h < 2; ++h) {
            int mloc = mw + 16 * mg + 8 * h + q;
            int m = r0 + mloc;
            if (m >= N) continue;
            float ca = 1.f, sa = 0.f;
            if (COMBINE) { float a = angs[mloc]; ca = cosf(a); sa = sinf(a); }
#pragma unroll
            for (int j = 0; j < 4; ++j) {
                int col = nwq + 8 * j + 2 * t4;
                float2 val = make_float2(fin[mg][j][2 * h] * sk, fin[mg][j][2 * h + 1] * sk);
                if (COMBINE) {
                    const float* sp = SC + (size_t)m * 128 + col;
                    val.x = ca * sp[0] + sa * val.x;
                    val.y = ca * sp[1] + sa * val.y;
                }
                *(float2*)(C + (size_t)m * 128 + col) = val;
            }
        }
    }
}

template<bool COMBINE>
__global__ __launch_bounds__(512, 1)
void fctp_v(const float* __restrict__ X, const float* __restrict__ Y,
            const uint8_t* __restrict__ Bp, float* __restrict__ C,
            const float* __restrict__ SC, const float* __restrict__ W3, int N)
{
    extern __shared__ uint8_t smraw[];
    fctp_body<COMBINE>(blockIdx.x, smraw, X, Y, Bp, C, SC, W3, N);
}

// ---------------------------------------------------------------------------
// Edge MLP + scatter body (R8-proven)
// ---------------------------------------------------------------------------
__device__ __forceinline__ void edge_body(
    int tileIdx, __nv_bfloat16* sm,
    const float* __restrict__ ES,
    const __nv_bfloat16* __restrict__ B1h, const __nv_bfloat16* __restrict__ B1l,
    const __nv_bfloat16* __restrict__ B2h, const __nv_bfloat16* __restrict__ B2l,
    const float* __restrict__ SF, const int* __restrict__ SRC,
    const int* __restrict__ DST, const float* __restrict__ EA,
    float* __restrict__ RF, int E)
{
    __nv_bfloat16* b1h = sm;              // [128][72]
    __nv_bfloat16* b1l = sm + 9216;
    __nv_bfloat16* b2h = sm + 18432;      // [128][136]
    __nv_bfloat16* b2l = sm + 35840;

    const int tid = threadIdx.x, wid = tid >> 5, lane = tid & 31;
    const int e0 = tileIdx * 256;
    const int q = lane >> 2, t4 = lane & 3, grp = lane >> 3, rw = lane & 7;

    for (int i = tid; i < 1024; i += 512) {
        int n = i >> 3, seg = i & 7;
        *(uint4*)(b1h + n * 72 + seg * 8) = *(const uint4*)(B1h + (size_t)n * 64 + seg * 8);
        *(uint4*)(b1l + n * 72 + seg * 8) = *(const uint4*)(B1l + (size_t)n * 64 + seg * 8);
    }
    for (int i = tid; i < 2048; i += 512) {
        int n = i >> 4, seg = i & 15;
        *(uint4*)(b2h + n * 136 + seg * 8) = *(const uint4*)(B2h + (size_t)n * 128 + seg * 8);
        *(uint4*)(b2l + n * 136 + seg * 8) = *(const uint4*)(B2l + (size_t)n * 128 + seg * 8);
    }
    __syncthreads();

    const uint32_t s1h = smem_u32(b1h), s1l = smem_u32(b1l);
    const uint32_t s2h = smem_u32(b2h), s2l = smem_u32(b2l);

    const int r0e = e0 + wid * 16 + q, r1e = r0e + 8;
    const int ce0 = (r0e < E) ? r0e : 0, ce1 = (r1e < E) ? r1e : 0;
    const float* es0 = ES + (size_t)ce0 * 64;
    const float* es1 = ES + (size_t)ce1 * 64;

    float acc1[16][4];
#pragma unroll
    for (int j = 0; j < 16; ++j)
#pragma unroll
        for (int i = 0; i < 4; ++i) acc1[j][i] = 0.f;

    // GEMM1: [256x64] @ [64x128]; A from gmem
#pragma unroll
    for (int s = 0; s < 4; ++s) {
        float2 x0a = *(const float2*)(es0 + s * 16 + 2 * t4);
        float2 x0b = *(const float2*)(es1 + s * 16 + 2 * t4);
        float2 x1a = *(const float2*)(es0 + s * 16 + 8 + 2 * t4);
        float2 x1b = *(const float2*)(es1 + s * 16 + 8 + 2 * t4);
        uint32_t ah[4], al[4];
        ah[0] = pack_hi(x0a.x, x0a.y); al[0] = pack_lo(x0a.x, x0a.y, ah[0]);
        ah[1] = pack_hi(x0b.x, x0b.y); al[1] = pack_lo(x0b.x, x0b.y, ah[1]);
        ah[2] = pack_hi(x1a.x, x1a.y); al[2] = pack_lo(x1a.x, x1a.y, ah[2]);
        ah[3] = pack_hi(x1b.x, x1b.y); al[3] = pack_lo(x1b.x, x1b.y, ah[3]);
#pragma unroll
        for (int jj = 0; jj < 8; ++jj) {
            int nrow = 8 * (2 * jj + (grp >> 1)) + rw;
            int kc = s * 16 + (grp & 1) * 8;
            uint32_t off = (uint32_t)(nrow * 72 + kc) * 2;
            uint32_t bh[4], bl[4];
            ldsm4(bh, s1h + off);
            ldsm4(bl, s1l + off);
            mma16816(acc1[2 * jj],     ah, bh);
            mma16816(acc1[2 * jj + 1], ah, bh + 2);
            mma16816(acc1[2 * jj],     al, bh);
            mma16816(acc1[2 * jj + 1], al, bh + 2);
            mma16816(acc1[2 * jj],     ah, bl);
            mma16816(acc1[2 * jj + 1], ah, bl + 2);
        }
    }

    // silu + pack A2 fragments (frees acc1)
    uint32_t pah[8][4], pal[8][4];
#pragma unroll
    for (int s = 0; s < 8; ++s) {
        float h00 = silu_n(acc1[2 * s][0]     * 0.125f);
        float h01 = silu_n(acc1[2 * s][1]     * 0.125f);
        float h02 = silu_n(acc1[2 * s][2]     * 0.125f);
        float h03 = silu_n(acc1[2 * s][3]     * 0.125f);
        float h10 = silu_n(acc1[2 * s + 1][0] * 0.125f);
        float h11 = silu_n(acc1[2 * s + 1][1] * 0.125f);
        float h12 = silu_n(acc1[2 * s + 1][2] * 0.125f);
        float h13 = silu_n(acc1[2 * s + 1][3] * 0.125f);
        pah[s][0] = pack_hi(h00, h01); pal[s][0] = pack_lo(h00, h01, pah[s][0]);
        pah[s][1] = pack_hi(h02, h03); pal[s][1] = pack_lo(h02, h03, pah[s][1]);
        pah[s][2] = pack_hi(h10, h11); pal[s][2] = pack_lo(h10, h11, pah[s][2]);
        pah[s][3] = pack_hi(h12, h13); pal[s][3] = pack_lo(h12, h13, pah[s][3]);
    }

    // GEMM2 + fused scatter, two 64-column halves
    const float sk = 0.08838834764831845f;   // 1/sqrt(128)
#pragma unroll
    for (int half = 0; half < 2; ++half) {
        float acc2[8][4];
#pragma unroll
        for (int j = 0; j < 8; ++j)
#pragma unroll
            for (int i = 0; i < 4; ++i) acc2[j][i] = 0.f;

#pragma unroll
        for (int s = 0; s < 8; ++s) {
#pragma unroll
            for (int jj = 0; jj < 4; ++jj) {
                int nrow = half * 64 + 8 * (2 * jj + (grp >> 1)) + rw;
                int kc = s * 16 + (grp & 1) * 8;
                uint32_t off = (uint32_t)(nrow * 136 + kc) * 2;
                uint32_t bh[4], bl[4];
                ldsm4(bh, s2h + off);
                ldsm4(bl, s2l + off);
                mma16816(acc2[2 * jj],     pah[s], bh);
                mma16816(acc2[2 * jj + 1], pah[s], bh + 2);
                mma16816(acc2[2 * jj],     pal[s], bh);
                mma16816(acc2[2 * jj + 1], pal[s], bh + 2);
                mma16816(acc2[2 * jj],     pah[s], bl);
                mma16816(acc2[2 * jj + 1], pah[s], bl + 2);
            }
        }

#pragma unroll
        for (int h = 0; h < 2; ++h) {
            int er = h ? r1e : r0e;
            if (er >= E) continue;
            int sidx = SRC[er], didx = DST[er];
            float ea = EA[er] * 0.17677669529663687f * sk;
            const float* sfr = SF + (size_t)sidx * 128 + half * 64;
            float* rfr = RF + (size_t)didx * 128 + half * 64;
#pragma unroll
            for (int j = 0; j < 8; ++j) {
                int col = 8 * j + 2 * t4;
                float2 s2 = *(const float2*)(sfr + col);
                redv2(rfr + col, acc2[j][2 * h] * ea * s2.x, acc2[j][2 * h + 1] * ea * s2.y);
            }
        }
    }
}

// ---------------------------------------------------------------------------
// Merged kernel: interleaved edge tiles + receiver-sc fctp tiles.
// bid%4==3 -> fctp tile (bid>>2); else edge tile (bid - ceil((bid+1)/4)).
// ---------------------------------------------------------------------------
__global__ __launch_bounds__(512, 1)
void edge_and_sc(const float* __restrict__ ES,
                 const __nv_bfloat16* __restrict__ B1h, const __nv_bfloat16* __restrict__ B1l,
                 const __nv_bfloat16* __restrict__ B2h, const __nv_bfloat16* __restrict__ B2l,
                 const float* __restrict__ SF, const int* __restrict__ SRC,
                 const int* __restrict__ DST, const float* __restrict__ EA,
                 float* __restrict__ RF, int E, int nEdgeTiles,
                 const float* __restrict__ Xr, const float* __restrict__ Yr,
                 const uint8_t* __restrict__ Bsc, float* __restrict__ SCout,
                 int Nr, int nScTiles)
{
    extern __shared__ uint8_t smraw[];
    const int g = blockIdx.x;
    if ((g & 3) == 3) {
        int f = g >> 2;
        if (f < nScTiles)
            fctp_body<false>(f, smraw, Xr, Yr, Bsc, SCout, nullptr, nullptr, Nr);
    } else {
        int e = g - ((g + 1) >> 2);
        if (e < nEdgeTiles)
            edge_body(e, (__nv_bfloat16*)smraw, ES, B1h, B1l, B2h, B2l,
                      SF, SRC, DST, EA, RF, E);
    }
}

// ---------------------------------------------------------------------------
extern "C" void kernel_launch(void* const* d_in, const int* in_sizes, int n_in,
                              void* d_out, int out_size)
{
    const float* sender_input   = (const float*)d_in[0];
    const float* sender_attr    = (const float*)d_in[1];
    const float* receiver_input = (const float*)d_in[2];
    const float* receiver_attr  = (const float*)d_in[3];
    const int*   edge_src       = (const int*)  d_in[4];
    const int*   edge_dst       = (const int*)  d_in[5];
    const float* edge_attr      = (const float*)d_in[6];
    const float* edge_scalars   = (const float*)d_in[7];
    const float* W_sc           = (const float*)d_in[8];
    const float* W_lin1         = (const float*)d_in[9];
    const float* W_fc1          = (const float*)d_in[10];
    const float* W_fc2          = (const float*)d_in[11];
    const float* W_lin2         = (const float*)d_in[12];
    const float* W_lin3         = (const float*)d_in[13];

    const int Ns = in_sizes[0] / 128;
    const int Nr = in_sizes[2] / 128;
    const int E  = in_sizes[4];

    float *sf_p, *sc_p, *rf_p;
    uint8_t* wp;
    cudaGetSymbolAddress((void**)&sf_p, g_sf);
    cudaGetSymbolAddress((void**)&sc_p, g_sc);
    cudaGetSymbolAddress((void**)&rf_p, g_rf);
    cudaGetSymbolAddress((void**)&wp,   g_wp);

    cudaFuncSetAttribute(edge_and_sc,   cudaFuncAttributeMaxDynamicSharedMemorySize, FCTP_SMEM);
    cudaFuncSetAttribute(fctp_v<false>, cudaFuncAttributeMaxDynamicSharedMemorySize, FCTP_SMEM);
    cudaFuncSetAttribute(fctp_v<true>,  cudaFuncAttributeMaxDynamicSharedMemorySize, FCTP_SMEM);

    // --- merged weight prep ---
    prep_all<<<816, 256>>>(W_fc1, W_fc2, W_lin1, W_sc, W_lin2, wp);

    cudaMemsetAsync(rf_p, 0, (size_t)Nr * 128 * sizeof(float));

    // --- sender features ---
    fctp_v<false><<<(Ns + 127) / 128, 512, FCTP_SMEM>>>(sender_input, sender_attr,
        wp + 4 * 262144, sf_p, nullptr, nullptr, Ns);

    // --- merged: edge MLP+scatter  ||  receiver self-connection fctp ---
    const int nE = (E + 255) / 256;
    const int nS = (Nr + 127) / 128;
    int grid = 4 * ((nS > (nE + 2) / 3) ? nS : (nE + 2) / 3);
    // ensure capacity on both sides
    while (grid - ((grid + 0) / 4 + ((grid % 4) > 3 ? 1 : 0)) - (grid / 4) < 0) grid += 4; // no-op safety
    if (grid - (grid / 4) < nE + 1) grid = ((nE * 4 + 2) / 3 + 3) & ~3;
    if (grid / 4 < nS) grid = 4 * nS;
    edge_and_sc<<<grid, 512, FCTP_SMEM>>>(
        edge_scalars,
        (const __nv_bfloat16*)wp, (const __nv_bfloat16*)(wp + 262144),
        (const __nv_bfloat16*)(wp + 2 * 262144), (const __nv_bfloat16*)(wp + 3 * 262144),
        sf_p, edge_src, edge_dst, edge_attr, rf_p, E, nE,
        receiver_input, receiver_attr, wp + 6 * 262144, sc_p, Nr, nS);

    // --- final fctp with fused angle + gating epilogue ---
    fctp_v<true><<<nS, 512, FCTP_SMEM>>>(rf_p, receiver_attr,
        wp + 8 * 262144, (float*)d_out, sc_p, W_lin3, Nr);
}

// round 13
// speedup vs baseline: 1.1396x; 1.0120x over previous
#include <cuda_runtime.h>
#include <cuda_bf16.h>
#include <math.h>
#include <stdint.h>

// ---------------------------------------------------------------------------
// Shapes: Ns=Nr=100000, E=600000, D=128, A=8, S=64, H=128
// ---------------------------------------------------------------------------
#define MAX_E 600000
#define MAX_N 100000

// Scratch (__device__ globals; allocation-free rule)
__device__ float g_sf [(size_t)MAX_N * 128];   // sender features
__device__ float g_sc [(size_t)MAX_N * 128];   // receiver self connection
__device__ float g_rf [(size_t)MAX_N * 128];   // scattered receiver features
__device__ float g_ang[(size_t)MAX_N];         // receiver angle
// Prepped weights, bf16; 256KB slots.
// slots 0/1: fc1 hi/lo  n-major [n][64]
// slots 2/3: fc2 hi/lo  n-major [n][128]
// slots 4/5: lin1 hi/lo v-major [v][n][k]  (8 x 128 x 128)
// slots 6/7: sc   hi/lo v-major
// slots 8/9: lin2 hi/lo v-major
__device__ __align__(1024) uint8_t g_wp[10][262144];

// ---------------------------------------------------------------------------
// mma.sync / ldmatrix / cp.async helpers (sm_80+/sm_90, no arch-a gating)
// ---------------------------------------------------------------------------
__device__ __forceinline__ uint32_t smem_u32(const void* p) {
    uint32_t a;
    asm("{ .reg .u64 t; cvta.to.shared.u64 t, %1; cvt.u32.u64 %0, t; }" : "=r"(a) : "l"(p));
    return a;
}

__device__ __forceinline__ void mma16816(float* d, const uint32_t* a, const uint32_t* b) {
    asm volatile(
        "mma.sync.aligned.m16n8k16.row.col.f32.bf16.bf16.f32 "
        "{%0,%1,%2,%3}, {%4,%5,%6,%7}, {%8,%9}, {%0,%1,%2,%3};"
        : "+f"(d[0]), "+f"(d[1]), "+f"(d[2]), "+f"(d[3])
        : "r"(a[0]), "r"(a[1]), "r"(a[2]), "r"(a[3]), "r"(b[0]), "r"(b[1]));
}

__device__ __forceinline__ void ldsm4(uint32_t* r, uint32_t addr) {
    asm volatile("ldmatrix.sync.aligned.m8n8.x4.shared.b16 {%0,%1,%2,%3}, [%4];"
                 : "=r"(r[0]), "=r"(r[1]), "=r"(r[2]), "=r"(r[3]) : "r"(addr));
}

__device__ __forceinline__ void cp16(uint32_t s, const void* g) {
    asm volatile("cp.async.cg.shared.global [%0], [%1], 16;"
                 :: "r"(s), "l"(g) : "memory");
}
#define CP_COMMIT() asm volatile("cp.async.commit_group;" ::: "memory")
#define CP_WAIT0()  asm volatile("cp.async.wait_group 0;" ::: "memory")

// vector float2 reduction (PTX 8.1, sm_90+)
__device__ __forceinline__ void redv2(float* addr, float a, float b) {
    asm volatile("red.global.add.v2.f32 [%0], {%1, %2};" :: "l"(addr), "f"(a), "f"(b) : "memory");
}

// pack two fp32 -> bf16x2 (hi), and residual (lo)
__device__ __forceinline__ uint32_t pack_hi(float a, float b) {
    __nv_bfloat162 h = __float22bfloat162_rn(make_float2(a, b));
    return *(uint32_t*)&h;
}
__device__ __forceinline__ uint32_t pack_lo(float a, float b, uint32_t hp) {
    __nv_bfloat162 h = *(__nv_bfloat162*)&hp;
    float2 hf = __bfloat1622float2(h);
    __nv_bfloat162 l = __float22bfloat162_rn(make_float2(a - hf.x, b - hf.y));
    return *(uint32_t*)&l;
}

__device__ __forceinline__ float silu_n(float x) {
    return 1.679177f * x / (1.f + expf(-x));
}

// ---------------------------------------------------------------------------
// Merged weight prep (ONE launch)
// ---------------------------------------------------------------------------
__global__ void prep_all(const float* __restrict__ Wfc1, const float* __restrict__ Wfc2,
                         const float* __restrict__ Wl1,  const float* __restrict__ Wsc,
                         const float* __restrict__ Wl2,  uint8_t* __restrict__ wp)
{
    int idx = blockIdx.x * blockDim.x + threadIdx.x;
    if (idx < 4096) {                    // fc1
        int n = idx >> 5, kp = (idx & 31) << 1;
        float a = Wfc1[(size_t)kp * 128 + n];
        float b = Wfc1[(size_t)(kp + 1) * 128 + n];
        uint32_t h = pack_hi(a, b), l = pack_lo(a, b, h);
        ((uint32_t*)(wp))[n * 32 + (kp >> 1)] = h;
        ((uint32_t*)(wp + 262144))[n * 32 + (kp >> 1)] = l;
    } else if (idx < 12288) {            // fc2
        int i = idx - 4096;
        int n = i >> 6, kp = (i & 63) << 1;
        float a = Wfc2[(size_t)kp * 128 + n];
        float b = Wfc2[(size_t)(kp + 1) * 128 + n];
        uint32_t h = pack_hi(a, b), l = pack_lo(a, b, h);
        ((uint32_t*)(wp + 2 * 262144))[n * 64 + (kp >> 1)] = h;
        ((uint32_t*)(wp + 3 * 262144))[n * 64 + (kp >> 1)] = l;
    } else if (idx < 208896) {           // lin weights, v-major
        int i = idx - 12288;
        int w = i >> 16;                 // 0=lin1 1=sc 2=lin2
        int r = i & 65535;
        int v = r >> 13, n = (r >> 6) & 127, up = r & 63, u = up << 1;
        const float* W = (w == 0) ? Wl1 : (w == 1) ? Wsc : Wl2;
        float a = W[(size_t)(u * 8 + v) * 128 + n];
        float b = W[(size_t)((u + 1) * 8 + v) * 128 + n];
        uint32_t h = pack_hi(a, b), l = pack_lo(a, b, h);
        ((uint32_t*)(wp + (size_t)(4 + 2 * w) * 262144))[v * 8192 + n * 64 + up] = h;
        ((uint32_t*)(wp + (size_t)(5 + 2 * w) * 262144))[v * 8192 + n * 64 + up] = l;
    }
}

// ---------------------------------------------------------------------------
// fctp body (R11-proven): out[m,w] = scale * sum_v Y[m,v] * (X @ W_v)[m,w]
// Tile: 128 nodes x 128 cols, 16 warps, warp tile 32m x 32n.
// COMBINE: out = cos(ANG[m])*SC + sin(ANG[m])*scale*acc.
// ---------------------------------------------------------------------------
static const int FCTP_SMEM = 212992;  // ys 4K + xh/xl 2x34816 + bh/bl 2x2x34816

template<bool COMBINE>
__device__ __forceinline__ void fctp_body(
    int tileIdx, uint8_t* smraw,
    const float* __restrict__ X, const float* __restrict__ Y,
    const uint8_t* __restrict__ Bp,   // hi slot base; lo at +262144
    float* __restrict__ C, const float* __restrict__ SC,
    const float* __restrict__ ANG, int N)
{
    float* ys = (float*)smraw;                                  // [128][8]
    __nv_bfloat16* xh = (__nv_bfloat16*)(smraw + 4096);         // [128][136]
    __nv_bfloat16* xl = xh + 17408;
    __nv_bfloat16* bh = xl + 17408;                             // [2][128][136]
    __nv_bfloat16* bl = bh + 34816;

    const int tid = threadIdx.x, wid = tid >> 5, lane = tid & 31;
    const int q = lane >> 2, t4 = lane & 3, grp = lane >> 3, rw = lane & 7;
    const int mw = (wid & 3) * 32, nwq = (wid >> 2) * 32;
    const int r0 = tileIdx * 128;
    const uint32_t xh_a = smem_u32(xh), xl_a = smem_u32(xl);
    const uint32_t bh_a = smem_u32(bh), bl_a = smem_u32(bl);

    auto stageB = [&](int v, int b) {
        const uint8_t* sh = Bp + (size_t)v * 32768;
        const uint8_t* sl = Bp + 262144 + (size_t)v * 32768;
#pragma unroll
        for (int t = 0; t < 4; ++t) {
            int idx = tid + t * 512;
            int n = idx >> 4, seg = idx & 15;
            uint32_t d = (uint32_t)(b * 34816 + n * 272 + seg * 16);
            cp16(bh_a + d, sh + n * 256 + seg * 16);
            cp16(bl_a + d, sl + n * 256 + seg * 16);
        }
    };

    stageB(0, 0); CP_COMMIT();

    // ys
    for (int i = tid; i < 1024; i += 512) {
        int n = i >> 3, v = i & 7, r = r0 + n;
        ys[i] = (r < N) ? Y[(size_t)r * 8 + v] : 0.f;
    }

    // X split hi/lo into smem (once per tile; plain stores, synced in loop)
    {
        int m = tid >> 2, quarter = tid & 3, r = r0 + m;
        const float* xr = X + (size_t)r * 128 + quarter * 32;
#pragma unroll
        for (int g = 0; g < 4; ++g) {
            float4 f0 = make_float4(0.f, 0.f, 0.f, 0.f), f1 = f0;
            if (r < N) {
                f0 = *(const float4*)(xr + g * 8);
                f1 = *(const float4*)(xr + g * 8 + 4);
            }
            uint32_t h[4], l[4];
            h[0] = pack_hi(f0.x, f0.y); l[0] = pack_lo(f0.x, f0.y, h[0]);
            h[1] = pack_hi(f0.z, f0.w); l[1] = pack_lo(f0.z, f0.w, h[1]);
            h[2] = pack_hi(f1.x, f1.y); l[2] = pack_lo(f1.x, f1.y, h[2]);
            h[3] = pack_hi(f1.z, f1.w); l[3] = pack_lo(f1.z, f1.w, h[3]);
            int eo = m * 136 + quarter * 32 + g * 8;
            *(uint4*)(xh + eo) = make_uint4(h[0], h[1], h[2], h[3]);
            *(uint4*)(xl + eo) = make_uint4(l[0], l[1], l[2], l[3]);
        }
    }

    float fin[2][4][4];
#pragma unroll
    for (int mg = 0; mg < 2; ++mg)
#pragma unroll
        for (int j = 0; j < 4; ++j)
#pragma unroll
            for (int i = 0; i < 4; ++i) fin[mg][j][i] = 0.f;

    for (int v = 0; v < 8; ++v) {
        CP_WAIT0();
        __syncthreads();
        if (v < 7) { stageB(v + 1, (v + 1) & 1); CP_COMMIT(); }

        const int b = v & 1;
        float tmp[2][4][4];
#pragma unroll
        for (int mg = 0; mg < 2; ++mg)
#pragma unroll
            for (int j = 0; j < 4; ++j)
#pragma unroll
                for (int i = 0; i < 4; ++i) tmp[mg][j][i] = 0.f;

#pragma unroll
        for (int kc = 0; kc < 8; ++kc) {
            uint32_t ah[2][4], al[2][4];
#pragma unroll
            for (int mg = 0; mg < 2; ++mg) {
                uint32_t ao = (uint32_t)((mw + 16 * mg + rw + (grp & 1) * 8) * 272
                                         + (kc * 16 + (grp >> 1) * 8) * 2);
                ldsm4(ah[mg], xh_a + ao);
                ldsm4(al[mg], xl_a + ao);
            }
#pragma unroll
            for (int jj = 0; jj < 2; ++jj) {
                int nrow = nwq + 8 * (2 * jj + (grp >> 1)) + rw;
                int kcol = kc * 16 + (grp & 1) * 8;
                uint32_t off = (uint32_t)(b * 34816 + nrow * 272 + kcol * 2);
                uint32_t bhf[4], blf[4];
                ldsm4(bhf, bh_a + off);
                ldsm4(blf, bl_a + off);
#pragma unroll
                for (int mg = 0; mg < 2; ++mg) {
                    mma16816(tmp[mg][2 * jj],     ah[mg], bhf);
                    mma16816(tmp[mg][2 * jj + 1], ah[mg], bhf + 2);
                    mma16816(tmp[mg][2 * jj],     al[mg], bhf);
                    mma16816(tmp[mg][2 * jj + 1], al[mg], bhf + 2);
                    mma16816(tmp[mg][2 * jj],     ah[mg], blf);
                    mma16816(tmp[mg][2 * jj + 1], ah[mg], blf + 2);
                }
            }
        }

        // fp32 Y-contraction (no extra rounding)
#pragma unroll
        for (int mg = 0; mg < 2; ++mg) {
            float yva = ys[(mw + 16 * mg + q) * 8 + v];
            float yvb = ys[(mw + 16 * mg + q + 8) * 8 + v];
#pragma unroll
            for (int j = 0; j < 4; ++j) {
                fin[mg][j][0] += yva * tmp[mg][j][0];
                fin[mg][j][1] += yva * tmp[mg][j][1];
                fin[mg][j][2] += yvb * tmp[mg][j][2];
                fin[mg][j][3] += yvb * tmp[mg][j][3];
            }
        }
    }

    // epilogue
    const float sk = 0.03125f;   // 1/sqrt(128*8)
#pragma unroll
    for (int mg = 0; mg < 2; ++mg) {
#pragma unroll
        for (int h = 0; h < 2; ++h) {
            int m = r0 + mw + 16 * mg + 8 * h + q;
            if (m >= N) continue;
            float ca = 1.f, sa = 0.f;
            if (COMBINE) { float a = ANG[m]; ca = cosf(a); sa = sinf(a); }
#pragma unroll
            for (int j = 0; j < 4; ++j) {
                int col = nwq + 8 * j + 2 * t4;
                float2 val = make_float2(fin[mg][j][2 * h] * sk, fin[mg][j][2 * h + 1] * sk);
                if (COMBINE) {
                    const float* sp = SC + (size_t)m * 128 + col;
                    val.x = ca * sp[0] + sa * val.x;
                    val.y = ca * sp[1] + sa * val.y;
                }
                *(float2*)(C + (size_t)m * 128 + col) = val;
            }
        }
    }
}

template<bool COMBINE>
__global__ __launch_bounds__(512, 1)
void fctp_v(const float* __restrict__ X, const float* __restrict__ Y,
            const uint8_t* __restrict__ Bp, float* __restrict__ C,
            const float* __restrict__ SC, const float* __restrict__ ANG, int N)
{
    extern __shared__ uint8_t smraw[];
    fctp_body<COMBINE>(blockIdx.x, smraw, X, Y, Bp, C, SC, ANG, N);
}

// ---------------------------------------------------------------------------
// Edge MLP + scatter body (R8-proven)
// ---------------------------------------------------------------------------
__device__ __forceinline__ void edge_body(
    int tileIdx, __nv_bfloat16* sm,
    const float* __restrict__ ES,
    const __nv_bfloat16* __restrict__ B1h, const __nv_bfloat16* __restrict__ B1l,
    const __nv_bfloat16* __restrict__ B2h, const __nv_bfloat16* __restrict__ B2l,
    const float* __restrict__ SF, const int* __restrict__ SRC,
    const int* __restrict__ DST, const float* __restrict__ EA,
    float* __restrict__ RF, int E)
{
    __nv_bfloat16* b1h = sm;              // [128][72]
    __nv_bfloat16* b1l = sm + 9216;
    __nv_bfloat16* b2h = sm + 18432;      // [128][136]
    __nv_bfloat16* b2l = sm + 35840;

    const int tid = threadIdx.x, wid = tid >> 5, lane = tid & 31;
    const int e0 = tileIdx * 256;
    const int q = lane >> 2, t4 = lane & 3, grp = lane >> 3, rw = lane & 7;

    for (int i = tid; i < 1024; i += 512) {
        int n = i >> 3, seg = i & 7;
        *(uint4*)(b1h + n * 72 + seg * 8) = *(const uint4*)(B1h + (size_t)n * 64 + seg * 8);
        *(uint4*)(b1l + n * 72 + seg * 8) = *(const uint4*)(B1l + (size_t)n * 64 + seg * 8);
    }
    for (int i = tid; i < 2048; i += 512) {
        int n = i >> 4, seg = i & 15;
        *(uint4*)(b2h + n * 136 + seg * 8) = *(const uint4*)(B2h + (size_t)n * 128 + seg * 8);
        *(uint4*)(b2l + n * 136 + seg * 8) = *(const uint4*)(B2l + (size_t)n * 128 + seg * 8);
    }
    __syncthreads();

    const uint32_t s1h = smem_u32(b1h), s1l = smem_u32(b1l);
    const uint32_t s2h = smem_u32(b2h), s2l = smem_u32(b2l);

    const int r0e = e0 + wid * 16 + q, r1e = r0e + 8;
    const int ce0 = (r0e < E) ? r0e : 0, ce1 = (r1e < E) ? r1e : 0;
    const float* es0 = ES + (size_t)ce0 * 64;
    const float* es1 = ES + (size_t)ce1 * 64;

    float acc1[16][4];
#pragma unroll
    for (int j = 0; j < 16; ++j)
#pragma unroll
        for (int i = 0; i < 4; ++i) acc1[j][i] = 0.f;

    // GEMM1: [256x64] @ [64x128]; A from gmem
#pragma unroll
    for (int s = 0; s < 4; ++s) {
        float2 x0a = *(const float2*)(es0 + s * 16 + 2 * t4);
        float2 x0b = *(const float2*)(es1 + s * 16 + 2 * t4);
        float2 x1a = *(const float2*)(es0 + s * 16 + 8 + 2 * t4);
        float2 x1b = *(const float2*)(es1 + s * 16 + 8 + 2 * t4);
        uint32_t ah[4], al[4];
        ah[0] = pack_hi(x0a.x, x0a.y); al[0] = pack_lo(x0a.x, x0a.y, ah[0]);
        ah[1] = pack_hi(x0b.x, x0b.y); al[1] = pack_lo(x0b.x, x0b.y, ah[1]);
        ah[2] = pack_hi(x1a.x, x1a.y); al[2] = pack_lo(x1a.x, x1a.y, ah[2]);
        ah[3] = pack_hi(x1b.x, x1b.y); al[3] = pack_lo(x1b.x, x1b.y, ah[3]);
#pragma unroll
        for (int jj = 0; jj < 8; ++jj) {
            int nrow = 8 * (2 * jj + (grp >> 1)) + rw;
            int kc = s * 16 + (grp & 1) * 8;
            uint32_t off = (uint32_t)(nrow * 72 + kc) * 2;
            uint32_t bh[4], bl[4];
            ldsm4(bh, s1h + off);
            ldsm4(bl, s1l + off);
            mma16816(acc1[2 * jj],     ah, bh);
            mma16816(acc1[2 * jj + 1], ah, bh + 2);
            mma16816(acc1[2 * jj],     al, bh);
            mma16816(acc1[2 * jj + 1], al, bh + 2);
            mma16816(acc1[2 * jj],     ah, bl);
            mma16816(acc1[2 * jj + 1], ah, bl + 2);
        }
    }

    // silu + pack A2 fragments (frees acc1)
    uint32_t pah[8][4], pal[8][4];
#pragma unroll
    for (int s = 0; s < 8; ++s) {
        float h00 = silu_n(acc1[2 * s][0]     * 0.125f);
        float h01 = silu_n(acc1[2 * s][1]     * 0.125f);
        float h02 = silu_n(acc1[2 * s][2]     * 0.125f);
        float h03 = silu_n(acc1[2 * s][3]     * 0.125f);
        float h10 = silu_n(acc1[2 * s + 1][0] * 0.125f);
        float h11 = silu_n(acc1[2 * s + 1][1] * 0.125f);
        float h12 = silu_n(acc1[2 * s + 1][2] * 0.125f);
        float h13 = silu_n(acc1[2 * s + 1][3] * 0.125f);
        pah[s][0] = pack_hi(h00, h01); pal[s][0] = pack_lo(h00, h01, pah[s][0]);
        pah[s][1] = pack_hi(h02, h03); pal[s][1] = pack_lo(h02, h03, pah[s][1]);
        pah[s][2] = pack_hi(h10, h11); pal[s][2] = pack_lo(h10, h11, pah[s][2]);
        pah[s][3] = pack_hi(h12, h13); pal[s][3] = pack_lo(h12, h13, pah[s][3]);
    }

    // GEMM2 + fused scatter, two 64-column halves
    const float sk = 0.08838834764831845f;   // 1/sqrt(128)
#pragma unroll
    for (int half = 0; half < 2; ++half) {
        float acc2[8][4];
#pragma unroll
        for (int j = 0; j < 8; ++j)
#pragma unroll
            for (int i = 0; i < 4; ++i) acc2[j][i] = 0.f;

#pragma unroll
        for (int s = 0; s < 8; ++s) {
#pragma unroll
            for (int jj = 0; jj < 4; ++jj) {
                int nrow = half * 64 + 8 * (2 * jj + (grp >> 1)) + rw;
                int kc = s * 16 + (grp & 1) * 8;
                uint32_t off = (uint32_t)(nrow * 136 + kc) * 2;
                uint32_t bh[4], bl[4];
                ldsm4(bh, s2h + off);
                ldsm4(bl, s2l + off);
                mma16816(acc2[2 * jj],     pah[s], bh);
                mma16816(acc2[2 * jj + 1], pah[s], bh + 2);
                mma16816(acc2[2 * jj],     pal[s], bh);
                mma16816(acc2[2 * jj + 1], pal[s], bh + 2);
                mma16816(acc2[2 * jj],     pah[s], bl);
                mma16816(acc2[2 * jj + 1], pah[s], bl + 2);
            }
        }

#pragma unroll
        for (int h = 0; h < 2; ++h) {
            int er = h ? r1e : r0e;
            if (er >= E) continue;
            int sidx = SRC[er], didx = DST[er];
            float ea = EA[er] * 0.17677669529663687f * sk;
            const float* sfr = SF + (size_t)sidx * 128 + half * 64;
            float* rfr = RF + (size_t)didx * 128 + half * 64;
#pragma unroll
            for (int j = 0; j < 8; ++j) {
                int col = 8 * j + 2 * t4;
                float2 s2 = *(const float2*)(sfr + col);
                redv2(rfr + col, acc2[j][2 * h] * ea * s2.x, acc2[j][2 * h + 1] * ea * s2.y);
            }
        }
    }
}

// ---------------------------------------------------------------------------
// Merged kernel: interleaved edge tiles + receiver-sc fctp tiles (3:1).
// ---------------------------------------------------------------------------
__global__ __launch_bounds__(512, 1)
void edge_and_sc(const float* __restrict__ ES,
                 const __nv_bfloat16* __restrict__ B1h, const __nv_bfloat16* __restrict__ B1l,
                 const __nv_bfloat16* __restrict__ B2h, const __nv_bfloat16* __restrict__ B2l,
                 const float* __restrict__ SF, const int* __restrict__ SRC,
                 const int* __restrict__ DST, const float* __restrict__ EA,
                 float* __restrict__ RF, int E, int nEdgeTiles,
                 const float* __restrict__ Xr, const float* __restrict__ Yr,
                 const uint8_t* __restrict__ Bsc, float* __restrict__ SCout,
                 int Nr, int nScTiles)
{
    extern __shared__ uint8_t smraw[];
    const int g = blockIdx.x;
    if ((g & 3) == 3) {
        int f = g >> 2;
        if (f < nScTiles)
            fctp_body<false>(f, smraw, Xr, Yr, Bsc, SCout, nullptr, nullptr, Nr);
    } else {
        int e = g - ((g + 1) >> 2);
        if (e < nEdgeTiles)
            edge_body(e, (__nv_bfloat16*)smraw, ES, B1h, B1l, B2h, B2l,
                      SF, SRC, DST, EA, RF, E);
    }
}

// ---------------------------------------------------------------------------
// Angle: ang[n] = 0.1/32 * sum_{u,v} rf[n,u] rattr[n,v] W3[u*8+v]; warp/node
// ---------------------------------------------------------------------------
__global__ void angle_kernel(const float* __restrict__ RF, const float* __restrict__ RA,
                             const float* __restrict__ W3, float* __restrict__ ANG, int N)
{
    int gw   = (blockIdx.x * blockDim.x + threadIdx.x) >> 5;
    int lane = threadIdx.x & 31;
    if (gw >= N) return;
    float ya[8];
#pragma unroll
    for (int v = 0; v < 8; ++v) ya[v] = RA[(size_t)gw * 8 + v];
    float sacc = 0.f;
#pragma unroll
    for (int uu = 0; uu < 4; ++uu) {
        int u = lane + uu * 32;
        float xv = RF[(size_t)gw * 128 + u];
#pragma unroll
        for (int v = 0; v < 8; ++v) sacc += xv * ya[v] * W3[u * 8 + v];
    }
#pragma unroll
    for (int off = 16; off; off >>= 1) sacc += __shfl_xor_sync(0xffffffffu, sacc, off);
    if (lane == 0) ANG[gw] = 0.003125f * sacc;   // 0.1 / 32
}

// ---------------------------------------------------------------------------
extern "C" void kernel_launch(void* const* d_in, const int* in_sizes, int n_in,
                              void* d_out, int out_size)
{
    const float* sender_input   = (const float*)d_in[0];
    const float* sender_attr    = (const float*)d_in[1];
    const float* receiver_input = (const float*)d_in[2];
    const float* receiver_attr  = (const float*)d_in[3];
    const int*   edge_src       = (const int*)  d_in[4];
    const int*   edge_dst       = (const int*)  d_in[5];
    const float* edge_attr      = (const float*)d_in[6];
    const float* edge_scalars   = (const float*)d_in[7];
    const float* W_sc           = (const float*)d_in[8];
    const float* W_lin1         = (const float*)d_in[9];
    const float* W_fc1          = (const float*)d_in[10];
    const float* W_fc2          = (const float*)d_in[11];
    const float* W_lin2         = (const float*)d_in[12];
    const float* W_lin3         = (const float*)d_in[13];

    const int Ns = in_sizes[0] / 128;
    const int Nr = in_sizes[2] / 128;
    const int E  = in_sizes[4];

    float *sf_p, *sc_p, *rf_p, *ang_p;
    uint8_t* wp;
    cudaGetSymbolAddress((void**)&sf_p,  g_sf);
    cudaGetSymbolAddress((void**)&sc_p,  g_sc);
    cudaGetSymbolAddress((void**)&rf_p,  g_rf);
    cudaGetSymbolAddress((void**)&ang_p, g_ang);
    cudaGetSymbolAddress((void**)&wp,    g_wp);

    cudaFuncSetAttribute(edge_and_sc,   cudaFuncAttributeMaxDynamicSharedMemorySize, FCTP_SMEM);
    cudaFuncSetAttribute(fctp_v<false>, cudaFuncAttributeMaxDynamicSharedMemorySize, FCTP_SMEM);
    cudaFuncSetAttribute(fctp_v<true>,  cudaFuncAttributeMaxDynamicSharedMemorySize, FCTP_SMEM);

    // --- merged weight prep ---
    prep_all<<<816, 256>>>(W_fc1, W_fc2, W_lin1, W_sc, W_lin2, wp);

    cudaMemsetAsync(rf_p, 0, (size_t)Nr * 128 * sizeof(float));

    // --- sender features ---
    fctp_v<false><<<(Ns + 127) / 128, 512, FCTP_SMEM>>>(sender_input, sender_attr,
        wp + 4 * 262144, sf_p, nullptr, nullptr, Ns);

    // --- merged: edge MLP+scatter  ||  receiver self-connection fctp ---
    const int nE = (E + 255) / 256;
    const int nS = (Nr + 127) / 128;
    int grid = 4 * ((nS > (nE + 2) / 3) ? nS : (nE + 2) / 3);
    if (grid - (grid / 4) < nE + 1) grid = ((nE * 4 + 2) / 3 + 3) & ~3;
    if (grid / 4 < nS) grid = 4 * nS;
    edge_and_sc<<<grid, 512, FCTP_SMEM>>>(
        edge_scalars,
        (const __nv_bfloat16*)wp, (const __nv_bfloat16*)(wp + 262144),
        (const __nv_bfloat16*)(wp + 2 * 262144), (const __nv_bfloat16*)(wp + 3 * 262144),
        sf_p, edge_src, edge_dst, edge_attr, rf_p, E, nE,
        receiver_input, receiver_attr, wp + 6 * 262144, sc_p, Nr, nS);

    // --- angle (warp/node) + final fctp with gating epilogue ---
    angle_kernel<<<((long long)Nr * 32 + 255) / 256, 256>>>(rf_p, receiver_attr, W_lin3, ang_p, Nr);
    fctp_v<true><<<nS, 512, FCTP_SMEM>>>(rf_p, receiver_attr,
        wp + 8 * 262144, (float*)d_out, sc_p, ang_p, Nr);
}

// round 14
// speedup vs baseline: 1.2097x; 1.0615x over previous
#include <cuda_runtime.h>
#include <cuda_bf16.h>
#include <math.h>
#include <stdint.h>

// ---------------------------------------------------------------------------
// Shapes: Ns=Nr=100000, E=600000, D=128, A=8, S=64, H=128
// ---------------------------------------------------------------------------
#define MAX_E 600000
#define MAX_N 100000

// Scratch (__device__ globals; allocation-free rule)
__device__ float g_sf [(size_t)MAX_N * 128];   // sender features
__device__ float g_sc [(size_t)MAX_N * 128];   // receiver self connection
__device__ float g_rf [(size_t)MAX_N * 128];   // scattered receiver features
__device__ float g_ang[(size_t)MAX_N];         // receiver angle
// Prepped weights, bf16; 256KB slots.
// slots 0/1: fc1 hi/lo  n-major [n][64]
// slots 2/3: fc2 hi/lo  n-major [n][128]
// slots 4/5: lin1 hi/lo v-major [v][n][k]  (8 x 128 x 128)
// slots 6/7: sc   hi/lo v-major
// slots 8/9: lin2 hi/lo v-major
__device__ __align__(1024) uint8_t g_wp[10][262144];

// ---------------------------------------------------------------------------
// mma.sync / ldmatrix / cp.async helpers (sm_80+/sm_90, no arch-a gating)
// ---------------------------------------------------------------------------
__device__ __forceinline__ uint32_t smem_u32(const void* p) {
    uint32_t a;
    asm("{ .reg .u64 t; cvta.to.shared.u64 t, %1; cvt.u32.u64 %0, t; }" : "=r"(a) : "l"(p));
    return a;
}

__device__ __forceinline__ void mma16816(float* d, const uint32_t* a, const uint32_t* b) {
    asm volatile(
        "mma.sync.aligned.m16n8k16.row.col.f32.bf16.bf16.f32 "
        "{%0,%1,%2,%3}, {%4,%5,%6,%7}, {%8,%9}, {%0,%1,%2,%3};"
        : "+f"(d[0]), "+f"(d[1]), "+f"(d[2]), "+f"(d[3])
        : "r"(a[0]), "r"(a[1]), "r"(a[2]), "r"(a[3]), "r"(b[0]), "r"(b[1]));
}

__device__ __forceinline__ void ldsm4(uint32_t* r, uint32_t addr) {
    asm volatile("ldmatrix.sync.aligned.m8n8.x4.shared.b16 {%0,%1,%2,%3}, [%4];"
                 : "=r"(r[0]), "=r"(r[1]), "=r"(r[2]), "=r"(r[3]) : "r"(addr));
}

__device__ __forceinline__ void cp16(uint32_t s, const void* g) {
    asm volatile("cp.async.cg.shared.global [%0], [%1], 16;"
                 :: "r"(s), "l"(g) : "memory");
}
#define CP_COMMIT() asm volatile("cp.async.commit_group;" ::: "memory")
#define CP_WAIT0()  asm volatile("cp.async.wait_group 0;" ::: "memory")

// vector float2 reduction (PTX 8.1, sm_90+)
__device__ __forceinline__ void redv2(float* addr, float a, float b) {
    asm volatile("red.global.add.v2.f32 [%0], {%1, %2};" :: "l"(addr), "f"(a), "f"(b) : "memory");
}

// pack two fp32 -> bf16x2 (hi), and residual (lo)
__device__ __forceinline__ uint32_t pack_hi(float a, float b) {
    __nv_bfloat162 h = __float22bfloat162_rn(make_float2(a, b));
    return *(uint32_t*)&h;
}
__device__ __forceinline__ uint32_t pack_lo(float a, float b, uint32_t hp) {
    __nv_bfloat162 h = *(__nv_bfloat162*)&hp;
    float2 hf = __bfloat1622float2(h);
    __nv_bfloat162 l = __float22bfloat162_rn(make_float2(a - hf.x, b - hf.y));
    return *(uint32_t*)&l;
}

__device__ __forceinline__ float silu_n(float x) {
    return 1.679177f * x / (1.f + expf(-x));
}

// ---------------------------------------------------------------------------
// Merged weight prep (ONE launch)
// ---------------------------------------------------------------------------
__global__ void prep_all(const float* __restrict__ Wfc1, const float* __restrict__ Wfc2,
                         const float* __restrict__ Wl1,  const float* __restrict__ Wsc,
                         const float* __restrict__ Wl2,  uint8_t* __restrict__ wp)
{
    int idx = blockIdx.x * blockDim.x + threadIdx.x;
    if (idx < 4096) {                    // fc1
        int n = idx >> 5, kp = (idx & 31) << 1;
        float a = Wfc1[(size_t)kp * 128 + n];
        float b = Wfc1[(size_t)(kp + 1) * 128 + n];
        uint32_t h = pack_hi(a, b), l = pack_lo(a, b, h);
        ((uint32_t*)(wp))[n * 32 + (kp >> 1)] = h;
        ((uint32_t*)(wp + 262144))[n * 32 + (kp >> 1)] = l;
    } else if (idx < 12288) {            // fc2
        int i = idx - 4096;
        int n = i >> 6, kp = (i & 63) << 1;
        float a = Wfc2[(size_t)kp * 128 + n];
        float b = Wfc2[(size_t)(kp + 1) * 128 + n];
        uint32_t h = pack_hi(a, b), l = pack_lo(a, b, h);
        ((uint32_t*)(wp + 2 * 262144))[n * 64 + (kp >> 1)] = h;
        ((uint32_t*)(wp + 3 * 262144))[n * 64 + (kp >> 1)] = l;
    } else if (idx < 208896) {           // lin weights, v-major
        int i = idx - 12288;
        int w = i >> 16;                 // 0=lin1 1=sc 2=lin2
        int r = i & 65535;
        int v = r >> 13, n = (r >> 6) & 127, up = r & 63, u = up << 1;
        const float* W = (w == 0) ? Wl1 : (w == 1) ? Wsc : Wl2;
        float a = W[(size_t)(u * 8 + v) * 128 + n];
        float b = W[(size_t)((u + 1) * 8 + v) * 128 + n];
        uint32_t h = pack_hi(a, b), l = pack_lo(a, b, h);
        ((uint32_t*)(wp + (size_t)(4 + 2 * w) * 262144))[v * 8192 + n * 64 + up] = h;
        ((uint32_t*)(wp + (size_t)(5 + 2 * w) * 262144))[v * 8192 + n * 64 + up] = l;
    }
}

// ---------------------------------------------------------------------------
// fctp body (R11-proven): out[m,w] = scale * sum_v Y[m,v] * (X @ W_v)[m,w]
// Tile: 128 nodes x 128 cols, 16 warps, warp tile 32m x 32n.
// COMBINE: out = cos(ANG[m])*SC + sin(ANG[m])*scale*acc.
// ---------------------------------------------------------------------------
static const int FCTP_SMEM = 212992;  // ys 4K + xh/xl 2x34816 + bh/bl 2x2x34816

template<bool COMBINE>
__device__ __forceinline__ void fctp_body(
    int tileIdx, uint8_t* smraw,
    const float* __restrict__ X, const float* __restrict__ Y,
    const uint8_t* __restrict__ Bp,   // hi slot base; lo at +262144
    float* __restrict__ C, const float* __restrict__ SC,
    const float* __restrict__ ANG, int N)
{
    float* ys = (float*)smraw;                                  // [128][8]
    __nv_bfloat16* xh = (__nv_bfloat16*)(smraw + 4096);         // [128][136]
    __nv_bfloat16* xl = xh + 17408;
    __nv_bfloat16* bh = xl + 17408;                             // [2][128][136]
    __nv_bfloat16* bl = bh + 34816;

    const int tid = threadIdx.x, wid = tid >> 5, lane = tid & 31;
    const int q = lane >> 2, t4 = lane & 3, grp = lane >> 3, rw = lane & 7;
    const int mw = (wid & 3) * 32, nwq = (wid >> 2) * 32;
    const int r0 = tileIdx * 128;
    const uint32_t xh_a = smem_u32(xh), xl_a = smem_u32(xl);
    const uint32_t bh_a = smem_u32(bh), bl_a = smem_u32(bl);

    auto stageB = [&](int v, int b) {
        const uint8_t* sh = Bp + (size_t)v * 32768;
        const uint8_t* sl = Bp + 262144 + (size_t)v * 32768;
#pragma unroll
        for (int t = 0; t < 4; ++t) {
            int idx = tid + t * 512;
            int n = idx >> 4, seg = idx & 15;
            uint32_t d = (uint32_t)(b * 34816 + n * 272 + seg * 16);
            cp16(bh_a + d, sh + n * 256 + seg * 16);
            cp16(bl_a + d, sl + n * 256 + seg * 16);
        }
    };

    stageB(0, 0); CP_COMMIT();

    // ys
    for (int i = tid; i < 1024; i += 512) {
        int n = i >> 3, v = i & 7, r = r0 + n;
        ys[i] = (r < N) ? Y[(size_t)r * 8 + v] : 0.f;
    }

    // X split hi/lo into smem (once per tile; plain stores, synced in loop)
    {
        int m = tid >> 2, quarter = tid & 3, r = r0 + m;
        const float* xr = X + (size_t)r * 128 + quarter * 32;
#pragma unroll
        for (int g = 0; g < 4; ++g) {
            float4 f0 = make_float4(0.f, 0.f, 0.f, 0.f), f1 = f0;
            if (r < N) {
                f0 = *(const float4*)(xr + g * 8);
                f1 = *(const float4*)(xr + g * 8 + 4);
            }
            uint32_t h[4], l[4];
            h[0] = pack_hi(f0.x, f0.y); l[0] = pack_lo(f0.x, f0.y, h[0]);
            h[1] = pack_hi(f0.z, f0.w); l[1] = pack_lo(f0.z, f0.w, h[1]);
            h[2] = pack_hi(f1.x, f1.y); l[2] = pack_lo(f1.x, f1.y, h[2]);
            h[3] = pack_hi(f1.z, f1.w); l[3] = pack_lo(f1.z, f1.w, h[3]);
            int eo = m * 136 + quarter * 32 + g * 8;
            *(uint4*)(xh + eo) = make_uint4(h[0], h[1], h[2], h[3]);
            *(uint4*)(xl + eo) = make_uint4(l[0], l[1], l[2], l[3]);
        }
    }

    float fin[2][4][4];
#pragma unroll
    for (int mg = 0; mg < 2; ++mg)
#pragma unroll
        for (int j = 0; j < 4; ++j)
#pragma unroll
            for (int i = 0; i < 4; ++i) fin[mg][j][i] = 0.f;

    for (int v = 0; v < 8; ++v) {
        CP_WAIT0();
        __syncthreads();
        if (v < 7) { stageB(v + 1, (v + 1) & 1); CP_COMMIT(); }

        const int b = v & 1;
        float tmp[2][4][4];
#pragma unroll
        for (int mg = 0; mg < 2; ++mg)
#pragma unroll
            for (int j = 0; j < 4; ++j)
#pragma unroll
                for (int i = 0; i < 4; ++i) tmp[mg][j][i] = 0.f;

#pragma unroll
        for (int kc = 0; kc < 8; ++kc) {
            uint32_t ah[2][4], al[2][4];
#pragma unroll
            for (int mg = 0; mg < 2; ++mg) {
                uint32_t ao = (uint32_t)((mw + 16 * mg + rw + (grp & 1) * 8) * 272
                                         + (kc * 16 + (grp >> 1) * 8) * 2);
                ldsm4(ah[mg], xh_a + ao);
                ldsm4(al[mg], xl_a + ao);
            }
#pragma unroll
            for (int jj = 0; jj < 2; ++jj) {
                int nrow = nwq + 8 * (2 * jj + (grp >> 1)) + rw;
                int kcol = kc * 16 + (grp & 1) * 8;
                uint32_t off = (uint32_t)(b * 34816 + nrow * 272 + kcol * 2);
                uint32_t bhf[4], blf[4];
                ldsm4(bhf, bh_a + off);
                ldsm4(blf, bl_a + off);
#pragma unroll
                for (int mg = 0; mg < 2; ++mg) {
                    mma16816(tmp[mg][2 * jj],     ah[mg], bhf);
                    mma16816(tmp[mg][2 * jj + 1], ah[mg], bhf + 2);
                    mma16816(tmp[mg][2 * jj],     al[mg], bhf);
                    mma16816(tmp[mg][2 * jj + 1], al[mg], bhf + 2);
                    mma16816(tmp[mg][2 * jj],     ah[mg], blf);
                    mma16816(tmp[mg][2 * jj + 1], ah[mg], blf + 2);
                }
            }
        }

        // fp32 Y-contraction (no extra rounding)
#pragma unroll
        for (int mg = 0; mg < 2; ++mg) {
            float yva = ys[(mw + 16 * mg + q) * 8 + v];
            float yvb = ys[(mw + 16 * mg + q + 8) * 8 + v];
#pragma unroll
            for (int j = 0; j < 4; ++j) {
                fin[mg][j][0] += yva * tmp[mg][j][0];
                fin[mg][j][1] += yva * tmp[mg][j][1];
                fin[mg][j][2] += yvb * tmp[mg][j][2];
                fin[mg][j][3] += yvb * tmp[mg][j][3];
            }
        }
    }

    // epilogue
    const float sk = 0.03125f;   // 1/sqrt(128*8)
#pragma unroll
    for (int mg = 0; mg < 2; ++mg) {
#pragma unroll
        for (int h = 0; h < 2; ++h) {
            int m = r0 + mw + 16 * mg + 8 * h + q;
            if (m >= N) continue;
            float ca = 1.f, sa = 0.f;
            if (COMBINE) { float a = ANG[m]; ca = cosf(a); sa = sinf(a); }
#pragma unroll
            for (int j = 0; j < 4; ++j) {
                int col = nwq + 8 * j + 2 * t4;
                float2 val = make_float2(fin[mg][j][2 * h] * sk, fin[mg][j][2 * h + 1] * sk);
                if (COMBINE) {
                    const float* sp = SC + (size_t)m * 128 + col;
                    val.x = ca * sp[0] + sa * val.x;
                    val.y = ca * sp[1] + sa * val.y;
                }
                *(float2*)(C + (size_t)m * 128 + col) = val;
            }
        }
    }
}

template<bool COMBINE>
__global__ __launch_bounds__(512, 1)
void fctp_v(const float* __restrict__ X, const float* __restrict__ Y,
            const uint8_t* __restrict__ Bp, float* __restrict__ C,
            const float* __restrict__ SC, const float* __restrict__ ANG, int N)
{
    extern __shared__ uint8_t smraw[];
    fctp_body<COMBINE>(blockIdx.x, smraw, X, Y, Bp, C, SC, ANG, N);
}

// ---------------------------------------------------------------------------
// Edge MLP + scatter body (R8-proven)
// ---------------------------------------------------------------------------
__device__ __forceinline__ void edge_body(
    int tileIdx, __nv_bfloat16* sm,
    const float* __restrict__ ES,
    const __nv_bfloat16* __restrict__ B1h, const __nv_bfloat16* __restrict__ B1l,
    const __nv_bfloat16* __restrict__ B2h, const __nv_bfloat16* __restrict__ B2l,
    const float* __restrict__ SF, const int* __restrict__ SRC,
    const int* __restrict__ DST, const float* __restrict__ EA,
    float* __restrict__ RF, int E)
{
    __nv_bfloat16* b1h = sm;              // [128][72]
    __nv_bfloat16* b1l = sm + 9216;
    __nv_bfloat16* b2h = sm + 18432;      // [128][136]
    __nv_bfloat16* b2l = sm + 35840;

    const int tid = threadIdx.x, wid = tid >> 5, lane = tid & 31;
    const int e0 = tileIdx * 256;
    const int q = lane >> 2, t4 = lane & 3, grp = lane >> 3, rw = lane & 7;

    for (int i = tid; i < 1024; i += 512) {
        int n = i >> 3, seg = i & 7;
        *(uint4*)(b1h + n * 72 + seg * 8) = *(const uint4*)(B1h + (size_t)n * 64 + seg * 8);
        *(uint4*)(b1l + n * 72 + seg * 8) = *(const uint4*)(B1l + (size_t)n * 64 + seg * 8);
    }
    for (int i = tid; i < 2048; i += 512) {
        int n = i >> 4, seg = i & 15;
        *(uint4*)(b2h + n * 136 + seg * 8) = *(const uint4*)(B2h + (size_t)n * 128 + seg * 8);
        *(uint4*)(b2l + n * 136 + seg * 8) = *(const uint4*)(B2l + (size_t)n * 128 + seg * 8);
    }
    __syncthreads();

    const uint32_t s1h = smem_u32(b1h), s1l = smem_u32(b1l);
    const uint32_t s2h = smem_u32(b2h), s2l = smem_u32(b2l);

    const int r0e = e0 + wid * 16 + q, r1e = r0e + 8;
    const int ce0 = (r0e < E) ? r0e : 0, ce1 = (r1e < E) ? r1e : 0;
    const float* es0 = ES + (size_t)ce0 * 64;
    const float* es1 = ES + (size_t)ce1 * 64;

    float acc1[16][4];
#pragma unroll
    for (int j = 0; j < 16; ++j)
#pragma unroll
        for (int i = 0; i < 4; ++i) acc1[j][i] = 0.f;

    // GEMM1: [256x64] @ [64x128]; A from gmem
#pragma unroll
    for (int s = 0; s < 4; ++s) {
        float2 x0a = *(const float2*)(es0 + s * 16 + 2 * t4);
        float2 x0b = *(const float2*)(es1 + s * 16 + 2 * t4);
        float2 x1a = *(const float2*)(es0 + s * 16 + 8 + 2 * t4);
        float2 x1b = *(const float2*)(es1 + s * 16 + 8 + 2 * t4);
        uint32_t ah[4], al[4];
        ah[0] = pack_hi(x0a.x, x0a.y); al[0] = pack_lo(x0a.x, x0a.y, ah[0]);
        ah[1] = pack_hi(x0b.x, x0b.y); al[1] = pack_lo(x0b.x, x0b.y, ah[1]);
        ah[2] = pack_hi(x1a.x, x1a.y); al[2] = pack_lo(x1a.x, x1a.y, ah[2]);
        ah[3] = pack_hi(x1b.x, x1b.y); al[3] = pack_lo(x1b.x, x1b.y, ah[3]);
#pragma unroll
        for (int jj = 0; jj < 8; ++jj) {
            int nrow = 8 * (2 * jj + (grp >> 1)) + rw;
            int kc = s * 16 + (grp & 1) * 8;
            uint32_t off = (uint32_t)(nrow * 72 + kc) * 2;
            uint32_t bh[4], bl[4];
            ldsm4(bh, s1h + off);
            ldsm4(bl, s1l + off);
            mma16816(acc1[2 * jj],     ah, bh);
            mma16816(acc1[2 * jj + 1], ah, bh + 2);
            mma16816(acc1[2 * jj],     al, bh);
            mma16816(acc1[2 * jj + 1], al, bh + 2);
            mma16816(acc1[2 * jj],     ah, bl);
            mma16816(acc1[2 * jj + 1], ah, bl + 2);
        }
    }

    // silu + pack A2 fragments (frees acc1)
    uint32_t pah[8][4], pal[8][4];
#pragma unroll
    for (int s = 0; s < 8; ++s) {
        float h00 = silu_n(acc1[2 * s][0]     * 0.125f);
        float h01 = silu_n(acc1[2 * s][1]     * 0.125f);
        float h02 = silu_n(acc1[2 * s][2]     * 0.125f);
        float h03 = silu_n(acc1[2 * s][3]     * 0.125f);
        float h10 = silu_n(acc1[2 * s + 1][0] * 0.125f);
        float h11 = silu_n(acc1[2 * s + 1][1] * 0.125f);
        float h12 = silu_n(acc1[2 * s + 1][2] * 0.125f);
        float h13 = silu_n(acc1[2 * s + 1][3] * 0.125f);
        pah[s][0] = pack_hi(h00, h01); pal[s][0] = pack_lo(h00, h01, pah[s][0]);
        pah[s][1] = pack_hi(h02, h03); pal[s][1] = pack_lo(h02, h03, pah[s][1]);
        pah[s][2] = pack_hi(h10, h11); pal[s][2] = pack_lo(h10, h11, pah[s][2]);
        pah[s][3] = pack_hi(h12, h13); pal[s][3] = pack_lo(h12, h13, pah[s][3]);
    }

    // GEMM2 + fused scatter, two 64-column halves
    const float sk = 0.08838834764831845f;   // 1/sqrt(128)
#pragma unroll
    for (int half = 0; half < 2; ++half) {
        float acc2[8][4];
#pragma unroll
        for (int j = 0; j < 8; ++j)
#pragma unroll
            for (int i = 0; i < 4; ++i) acc2[j][i] = 0.f;

#pragma unroll
        for (int s = 0; s < 8; ++s) {
#pragma unroll
            for (int jj = 0; jj < 4; ++jj) {
                int nrow = half * 64 + 8 * (2 * jj + (grp >> 1)) + rw;
                int kc = s * 16 + (grp & 1) * 8;
                uint32_t off = (uint32_t)(nrow * 136 + kc) * 2;
                uint32_t bh[4], bl[4];
                ldsm4(bh, s2h + off);
                ldsm4(bl, s2l + off);
                mma16816(acc2[2 * jj],     pah[s], bh);
                mma16816(acc2[2 * jj + 1], pah[s], bh + 2);
                mma16816(acc2[2 * jj],     pal[s], bh);
                mma16816(acc2[2 * jj + 1], pal[s], bh + 2);
                mma16816(acc2[2 * jj],     pah[s], bl);
                mma16816(acc2[2 * jj + 1], pah[s], bl + 2);
            }
        }

#pragma unroll
        for (int h = 0; h < 2; ++h) {
            int er = h ? r1e : r0e;
            if (er >= E) continue;
            int sidx = SRC[er], didx = DST[er];
            float ea = EA[er] * 0.17677669529663687f * sk;
            const float* sfr = SF + (size_t)sidx * 128 + half * 64;
            float* rfr = RF + (size_t)didx * 128 + half * 64;
#pragma unroll
            for (int j = 0; j < 8; ++j) {
                int col = 8 * j + 2 * t4;
                float2 s2 = *(const float2*)(sfr + col);
                redv2(rfr + col, acc2[j][2 * h] * ea * s2.x, acc2[j][2 * h + 1] * ea * s2.y);
            }
        }
    }
}

// ---------------------------------------------------------------------------
// Merged kernel: interleaved edge tiles + receiver-sc fctp tiles (3:1).
// ---------------------------------------------------------------------------
__global__ __launch_bounds__(512, 1)
void edge_and_sc(const float* __restrict__ ES,
                 const __nv_bfloat16* __restrict__ B1h, const __nv_bfloat16* __restrict__ B1l,
                 const __nv_bfloat16* __restrict__ B2h, const __nv_bfloat16* __restrict__ B2l,
                 const float* __restrict__ SF, const int* __restrict__ SRC,
                 const int* __restrict__ DST, const float* __restrict__ EA,
                 float* __restrict__ RF, int E, int nEdgeTiles,
                 const float* __restrict__ Xr, const float* __restrict__ Yr,
                 const uint8_t* __restrict__ Bsc, float* __restrict__ SCout,
                 int Nr, int nScTiles)
{
    extern __shared__ uint8_t smraw[];
    const int g = blockIdx.x;
    if ((g & 3) == 3) {
        int f = g >> 2;
        if (f < nScTiles)
            fctp_body<false>(f, smraw, Xr, Yr, Bsc, SCout, nullptr, nullptr, Nr);
    } else {
        int e = g - ((g + 1) >> 2);
        if (e < nEdgeTiles)
            edge_body(e, (__nv_bfloat16*)smraw, ES, B1h, B1l, B2h, B2l,
                      SF, SRC, DST, EA, RF, E);
    }
}

// ---------------------------------------------------------------------------
// Angle: ang[n] = 0.1/32 * sum_{u,v} rf[n,u] rattr[n,v] W3[u*8+v]
// W3 staged TRANSPOSED in smem (conflict-free LDS); 2 nodes per warp.
// ---------------------------------------------------------------------------
__global__ __launch_bounds__(256)
void angle_kernel(const float* __restrict__ RF, const float* __restrict__ RA,
                  const float* __restrict__ W3, float* __restrict__ ANG, int N)
{
    __shared__ float w3t[8][128];
    const int tid = threadIdx.x, lane = tid & 31, wrp = tid >> 5;

    for (int i = tid; i < 1024; i += 256) {
        int u = i & 127, v = i >> 7;
        w3t[v][u] = W3[u * 8 + v];
    }
    __syncthreads();

    const int base = (blockIdx.x * 8 + wrp) * 2;
#pragma unroll
    for (int h = 0; h < 2; ++h) {
        int n = base + h;
        if (n >= N) continue;
        float ya[8];
#pragma unroll
        for (int v = 0; v < 8; ++v) ya[v] = RA[(size_t)n * 8 + v];
        float sacc = 0.f;
#pragma unroll
        for (int uu = 0; uu < 4; ++uu) {
            int u = lane + uu * 32;
            float xv = RF[(size_t)n * 128 + u];
            float w = 0.f;
#pragma unroll
            for (int v = 0; v < 8; ++v) w += ya[v] * w3t[v][u];
            sacc += xv * w;
        }
#pragma unroll
        for (int off = 16; off; off >>= 1) sacc += __shfl_xor_sync(0xffffffffu, sacc, off);
        if (lane == 0) ANG[n] = 0.003125f * sacc;   // 0.1 / 32
    }
}

// ---------------------------------------------------------------------------
extern "C" void kernel_launch(void* const* d_in, const int* in_sizes, int n_in,
                              void* d_out, int out_size)
{
    const float* sender_input   = (const float*)d_in[0];
    const float* sender_attr    = (const float*)d_in[1];
    const float* receiver_input = (const float*)d_in[2];
    const float* receiver_attr  = (const float*)d_in[3];
    const int*   edge_src       = (const int*)  d_in[4];
    const int*   edge_dst       = (const int*)  d_in[5];
    const float* edge_attr      = (const float*)d_in[6];
    const float* edge_scalars   = (const float*)d_in[7];
    const float* W_sc           = (const float*)d_in[8];
    const float* W_lin1         = (const float*)d_in[9];
    const float* W_fc1          = (const float*)d_in[10];
    const float* W_fc2          = (const float*)d_in[11];
    const float* W_lin2         = (const float*)d_in[12];
    const float* W_lin3         = (const float*)d_in[13];

    const int Ns = in_sizes[0] / 128;
    const int Nr = in_sizes[2] / 128;
    const int E  = in_sizes[4];

    float *sf_p, *sc_p, *rf_p, *ang_p;
    uint8_t* wp;
    cudaGetSymbolAddress((void**)&sf_p,  g_sf);
    cudaGetSymbolAddress((void**)&sc_p,  g_sc);
    cudaGetSymbolAddress((void**)&rf_p,  g_rf);
    cudaGetSymbolAddress((void**)&ang_p, g_ang);
    cudaGetSymbolAddress((void**)&wp,    g_wp);

    cudaFuncSetAttribute(edge_and_sc,   cudaFuncAttributeMaxDynamicSharedMemorySize, FCTP_SMEM);
    cudaFuncSetAttribute(fctp_v<false>, cudaFuncAttributeMaxDynamicSharedMemorySize, FCTP_SMEM);
    cudaFuncSetAttribute(fctp_v<true>,  cudaFuncAttributeMaxDynamicSharedMemorySize, FCTP_SMEM);

    // --- merged weight prep ---
    prep_all<<<816, 256>>>(W_fc1, W_fc2, W_lin1, W_sc, W_lin2, wp);

    cudaMemsetAsync(rf_p, 0, (size_t)Nr * 128 * sizeof(float));

    // --- sender features ---
    fctp_v<false><<<(Ns + 127) / 128, 512, FCTP_SMEM>>>(sender_input, sender_attr,
        wp + 4 * 262144, sf_p, nullptr, nullptr, Ns);

    // --- merged: edge MLP+scatter  ||  receiver self-connection fctp ---
    const int nE = (E + 255) / 256;
    const int nS = (Nr + 127) / 128;
    int grid = 4 * ((nS > (nE + 2) / 3) ? nS : (nE + 2) / 3);
    if (grid - (grid / 4) < nE + 1) grid = ((nE * 4 + 2) / 3 + 3) & ~3;
    if (grid / 4 < nS) grid = 4 * nS;
    edge_and_sc<<<grid, 512, FCTP_SMEM>>>(
        edge_scalars,
        (const __nv_bfloat16*)wp, (const __nv_bfloat16*)(wp + 262144),
        (const __nv_bfloat16*)(wp + 2 * 262144), (const __nv_bfloat16*)(wp + 3 * 262144),
        sf_p, edge_src, edge_dst, edge_attr, rf_p, E, nE,
        receiver_input, receiver_attr, wp + 6 * 262144, sc_p, Nr, nS);

    // --- angle (smem W3t, 2 nodes/warp) + final fctp with gating epilogue ---
    angle_kernel<<<(Nr + 15) / 16, 256>>>(rf_p, receiver_attr, W_lin3, ang_p, Nr);
    fctp_v<true><<<nS, 512, FCTP_SMEM>>>(rf_p, receiver_attr,
        wp + 8 * 262144, (float*)d_out, sc_p, ang_p, Nr);
}

// round 15
// speedup vs baseline: 1.5740x; 1.3012x over previous
#include <cuda_runtime.h>
#include <cuda_fp16.h>
#include <math.h>
#include <stdint.h>

// ---------------------------------------------------------------------------
// Shapes: Ns=Nr=100000, E=600000, D=128, A=8, S=64, H=128
// Precision: fp16 2-pass (A split hi/lo fp16, B single fp16, fp32 accum).
// Per-term error ~2^-11 (B rounding); predicted rel_err ~1.5e-4 << 1e-3.
// ---------------------------------------------------------------------------
#define MAX_E 600000
#define MAX_N 100000

// Scratch (__device__ globals; allocation-free rule)
__device__ float g_sf [(size_t)MAX_N * 128];   // sender features
__device__ float g_sc [(size_t)MAX_N * 128];   // receiver self connection
__device__ float g_rf [(size_t)MAX_N * 128];   // scattered receiver features
__device__ float g_ang[(size_t)MAX_N];         // receiver angle
// Prepped weights, fp16 (single); 256KB slots.
// slot 0: fc1  n-major [n][64]
// slot 1: fc2  n-major [n][128]
// slot 2: lin1 v-major [v][n][k] (8 x 128 x 128)
// slot 3: sc   v-major
// slot 4: lin2 v-major
__device__ __align__(1024) uint8_t g_wp[5][262144];

// ---------------------------------------------------------------------------
// mma.sync / ldmatrix / cp.async helpers (sm_80+/sm_90, no arch-a gating)
// ---------------------------------------------------------------------------
__device__ __forceinline__ uint32_t smem_u32(const void* p) {
    uint32_t a;
    asm("{ .reg .u64 t; cvta.to.shared.u64 t, %1; cvt.u32.u64 %0, t; }" : "=r"(a) : "l"(p));
    return a;
}

__device__ __forceinline__ void mma16816(float* d, const uint32_t* a, const uint32_t* b) {
    asm volatile(
        "mma.sync.aligned.m16n8k16.row.col.f32.f16.f16.f32 "
        "{%0,%1,%2,%3}, {%4,%5,%6,%7}, {%8,%9}, {%0,%1,%2,%3};"
        : "+f"(d[0]), "+f"(d[1]), "+f"(d[2]), "+f"(d[3])
        : "r"(a[0]), "r"(a[1]), "r"(a[2]), "r"(a[3]), "r"(b[0]), "r"(b[1]));
}

__device__ __forceinline__ void ldsm4(uint32_t* r, uint32_t addr) {
    asm volatile("ldmatrix.sync.aligned.m8n8.x4.shared.b16 {%0,%1,%2,%3}, [%4];"
                 : "=r"(r[0]), "=r"(r[1]), "=r"(r[2]), "=r"(r[3]) : "r"(addr));
}

__device__ __forceinline__ void cp16(uint32_t s, const void* g) {
    asm volatile("cp.async.cg.shared.global [%0], [%1], 16;"
                 :: "r"(s), "l"(g) : "memory");
}
#define CP_COMMIT() asm volatile("cp.async.commit_group;" ::: "memory")
#define CP_WAIT0()  asm volatile("cp.async.wait_group 0;" ::: "memory")

// vector float2 reduction (PTX 8.1, sm_90+)
__device__ __forceinline__ void redv2(float* addr, float a, float b) {
    asm volatile("red.global.add.v2.f32 [%0], {%1, %2};" :: "l"(addr), "f"(a), "f"(b) : "memory");
}

// pack two fp32 -> fp16x2 (hi), and residual (lo)
__device__ __forceinline__ uint32_t pack_hi(float a, float b) {
    __half2 h = __floats2half2_rn(a, b);
    return *(uint32_t*)&h;
}
__device__ __forceinline__ uint32_t pack_lo(float a, float b, uint32_t hp) {
    __half2 h = *(__half2*)&hp;
    float2 hf = __half22float2(h);
    __half2 l = __floats2half2_rn(a - hf.x, b - hf.y);
    return *(uint32_t*)&l;
}

__device__ __forceinline__ float silu_n(float x) {
    return 1.679177f * x / (1.f + expf(-x));
}

// ---------------------------------------------------------------------------
// Merged weight prep (ONE launch): fp32 -> single fp16, prepped layouts
// ---------------------------------------------------------------------------
__global__ void prep_all(const float* __restrict__ Wfc1, const float* __restrict__ Wfc2,
                         const float* __restrict__ Wl1,  const float* __restrict__ Wsc,
                         const float* __restrict__ Wl2,  uint8_t* __restrict__ wp)
{
    int idx = blockIdx.x * blockDim.x + threadIdx.x;
    if (idx < 4096) {                    // fc1 [n][64]
        int n = idx >> 5, kp = (idx & 31) << 1;
        float a = Wfc1[(size_t)kp * 128 + n];
        float b = Wfc1[(size_t)(kp + 1) * 128 + n];
        ((uint32_t*)(wp))[n * 32 + (kp >> 1)] = pack_hi(a, b);
    } else if (idx < 12288) {            // fc2 [n][128]
        int i = idx - 4096;
        int n = i >> 6, kp = (i & 63) << 1;
        float a = Wfc2[(size_t)kp * 128 + n];
        float b = Wfc2[(size_t)(kp + 1) * 128 + n];
        ((uint32_t*)(wp + 262144))[n * 64 + (kp >> 1)] = pack_hi(a, b);
    } else if (idx < 208896) {           // lin weights, v-major [v][n][k]
        int i = idx - 12288;
        int w = i >> 16;                 // 0=lin1 1=sc 2=lin2
        int r = i & 65535;
        int v = r >> 13, n = (r >> 6) & 127, up = r & 63, u = up << 1;
        const float* W = (w == 0) ? Wl1 : (w == 1) ? Wsc : Wl2;
        float a = W[(size_t)(u * 8 + v) * 128 + n];
        float b = W[(size_t)((u + 1) * 8 + v) * 128 + n];
        ((uint32_t*)(wp + (size_t)(2 + w) * 262144))[v * 8192 + n * 64 + up] = pack_hi(a, b);
    }
}

// ---------------------------------------------------------------------------
// fctp body: out[m,w] = scale * sum_v Y[m,v] * (X @ W_v)[m,w]
// Tile: 128 nodes x 128 cols, 16 warps, warp tile 32m x 32n.
// A = fp16 hi/lo split of X (once per tile); B single fp16, double-buffered.
// 2 MMA passes: AhB + AlB.
// ---------------------------------------------------------------------------
static const int FCTP_SMEM = 143360;  // ys 4K + xh/xl 2x34816 + b 2x34816

template<bool COMBINE>
__device__ __forceinline__ void fctp_body(
    int tileIdx, uint8_t* smraw,
    const float* __restrict__ X, const float* __restrict__ Y,
    const uint8_t* __restrict__ Bp,   // fp16 weights, v-major
    float* __restrict__ C, const float* __restrict__ SC,
    const float* __restrict__ ANG, int N)
{
    float* ys = (float*)smraw;                            // [128][8]
    __half* xh = (__half*)(smraw + 4096);                 // [128][136]
    __half* xl = xh + 17408;
    __half* bb = xl + 17408;                              // [2][128][136]

    const int tid = threadIdx.x, wid = tid >> 5, lane = tid & 31;
    const int q = lane >> 2, t4 = lane & 3, grp = lane >> 3, rw = lane & 7;
    const int mw = (wid & 3) * 32, nwq = (wid >> 2) * 32;
    const int r0 = tileIdx * 128;
    const uint32_t xh_a = smem_u32(xh), xl_a = smem_u32(xl);
    const uint32_t bb_a = smem_u32(bb);

    auto stageB = [&](int v, int b) {
        const uint8_t* sh = Bp + (size_t)v * 32768;
#pragma unroll
        for (int t = 0; t < 4; ++t) {
            int idx = tid + t * 512;
            int n = idx >> 4, seg = idx & 15;
            cp16(bb_a + (uint32_t)(b * 34816 + n * 272 + seg * 16),
                 sh + n * 256 + seg * 16);
        }
    };

    stageB(0, 0); CP_COMMIT();

    // ys
    for (int i = tid; i < 1024; i += 512) {
        int n = i >> 3, v = i & 7, r = r0 + n;
        ys[i] = (r < N) ? Y[(size_t)r * 8 + v] : 0.f;
    }

    // X split hi/lo into smem (once per tile)
    {
        int m = tid >> 2, quarter = tid & 3, r = r0 + m;
        const float* xr = X + (size_t)r * 128 + quarter * 32;
#pragma unroll
        for (int g = 0; g < 4; ++g) {
            float4 f0 = make_float4(0.f, 0.f, 0.f, 0.f), f1 = f0;
            if (r < N) {
                f0 = *(const float4*)(xr + g * 8);
                f1 = *(const float4*)(xr + g * 8 + 4);
            }
            uint32_t h[4], l[4];
            h[0] = pack_hi(f0.x, f0.y); l[0] = pack_lo(f0.x, f0.y, h[0]);
            h[1] = pack_hi(f0.z, f0.w); l[1] = pack_lo(f0.z, f0.w, h[1]);
            h[2] = pack_hi(f1.x, f1.y); l[2] = pack_lo(f1.x, f1.y, h[2]);
            h[3] = pack_hi(f1.z, f1.w); l[3] = pack_lo(f1.z, f1.w, h[3]);
            int eo = m * 136 + quarter * 32 + g * 8;
            *(uint4*)(xh + eo) = make_uint4(h[0], h[1], h[2], h[3]);
            *(uint4*)(xl + eo) = make_uint4(l[0], l[1], l[2], l[3]);
        }
    }

    float fin[2][4][4];
#pragma unroll
    for (int mg = 0; mg < 2; ++mg)
#pragma unroll
        for (int j = 0; j < 4; ++j)
#pragma unroll
            for (int i = 0; i < 4; ++i) fin[mg][j][i] = 0.f;

    for (int v = 0; v < 8; ++v) {
        CP_WAIT0();
        __syncthreads();
        if (v < 7) { stageB(v + 1, (v + 1) & 1); CP_COMMIT(); }

        const int b = v & 1;
        float tmp[2][4][4];
#pragma unroll
        for (int mg = 0; mg < 2; ++mg)
#pragma unroll
            for (int j = 0; j < 4; ++j)
#pragma unroll
                for (int i = 0; i < 4; ++i) tmp[mg][j][i] = 0.f;

#pragma unroll
        for (int kc = 0; kc < 8; ++kc) {
            uint32_t ah[2][4], al[2][4];
#pragma unroll
            for (int mg = 0; mg < 2; ++mg) {
                uint32_t ao = (uint32_t)((mw + 16 * mg + rw + (grp & 1) * 8) * 272
                                         + (kc * 16 + (grp >> 1) * 8) * 2);
                ldsm4(ah[mg], xh_a + ao);
                ldsm4(al[mg], xl_a + ao);
            }
#pragma unroll
            for (int jj = 0; jj < 2; ++jj) {
                int nrow = nwq + 8 * (2 * jj + (grp >> 1)) + rw;
                int kcol = kc * 16 + (grp & 1) * 8;
                uint32_t off = (uint32_t)(b * 34816 + nrow * 272 + kcol * 2);
                uint32_t bf[4];
                ldsm4(bf, bb_a + off);
#pragma unroll
                for (int mg = 0; mg < 2; ++mg) {
                    mma16816(tmp[mg][2 * jj],     ah[mg], bf);
                    mma16816(tmp[mg][2 * jj + 1], ah[mg], bf + 2);
                    mma16816(tmp[mg][2 * jj],     al[mg], bf);
                    mma16816(tmp[mg][2 * jj + 1], al[mg], bf + 2);
                }
            }
        }

        // fp32 Y-contraction (no extra rounding)
#pragma unroll
        for (int mg = 0; mg < 2; ++mg) {
            float yva = ys[(mw + 16 * mg + q) * 8 + v];
            float yvb = ys[(mw + 16 * mg + q + 8) * 8 + v];
#pragma unroll
            for (int j = 0; j < 4; ++j) {
                fin[mg][j][0] += yva * tmp[mg][j][0];
                fin[mg][j][1] += yva * tmp[mg][j][1];
                fin[mg][j][2] += yvb * tmp[mg][j][2];
                fin[mg][j][3] += yvb * tmp[mg][j][3];
            }
        }
    }

    // epilogue
    const float sk = 0.03125f;   // 1/sqrt(128*8)
#pragma unroll
    for (int mg = 0; mg < 2; ++mg) {
#pragma unroll
        for (int h = 0; h < 2; ++h) {
            int m = r0 + mw + 16 * mg + 8 * h + q;
            if (m >= N) continue;
            float ca = 1.f, sa = 0.f;
            if (COMBINE) { float a = ANG[m]; ca = cosf(a); sa = sinf(a); }
#pragma unroll
            for (int j = 0; j < 4; ++j) {
                int col = nwq + 8 * j + 2 * t4;
                float2 val = make_float2(fin[mg][j][2 * h] * sk, fin[mg][j][2 * h + 1] * sk);
                if (COMBINE) {
                    const float* sp = SC + (size_t)m * 128 + col;
                    val.x = ca * sp[0] + sa * val.x;
                    val.y = ca * sp[1] + sa * val.y;
                }
                *(float2*)(C + (size_t)m * 128 + col) = val;
            }
        }
    }
}

template<bool COMBINE>
__global__ __launch_bounds__(512, 1)
void fctp_v(const float* __restrict__ X, const float* __restrict__ Y,
            const uint8_t* __restrict__ Bp, float* __restrict__ C,
            const float* __restrict__ SC, const float* __restrict__ ANG, int N)
{
    extern __shared__ uint8_t smraw[];
    fctp_body<COMBINE>(blockIdx.x, smraw, X, Y, Bp, C, SC, ANG, N);
}

// ---------------------------------------------------------------------------
// Edge MLP + scatter body (fp16 2-pass)
// ---------------------------------------------------------------------------
__device__ __forceinline__ void edge_body(
    int tileIdx, __half* sm,
    const float* __restrict__ ES,
    const __half* __restrict__ B1, const __half* __restrict__ B2,
    const float* __restrict__ SF, const int* __restrict__ SRC,
    const int* __restrict__ DST, const float* __restrict__ EA,
    float* __restrict__ RF, int E)
{
    __half* b1 = sm;              // [128][72]
    __half* b2 = sm + 9216;       // [128][136]

    const int tid = threadIdx.x, wid = tid >> 5, lane = tid & 31;
    const int e0 = tileIdx * 256;
    const int q = lane >> 2, t4 = lane & 3, grp = lane >> 3, rw = lane & 7;

    for (int i = tid; i < 1024; i += 512) {
        int n = i >> 3, seg = i & 7;
        *(uint4*)(b1 + n * 72 + seg * 8) = *(const uint4*)(B1 + (size_t)n * 64 + seg * 8);
    }
    for (int i = tid; i < 2048; i += 512) {
        int n = i >> 4, seg = i & 15;
        *(uint4*)(b2 + n * 136 + seg * 8) = *(const uint4*)(B2 + (size_t)n * 128 + seg * 8);
    }
    __syncthreads();

    const uint32_t s1 = smem_u32(b1), s2 = smem_u32(b2);

    const int r0e = e0 + wid * 16 + q, r1e = r0e + 8;
    const int ce0 = (r0e < E) ? r0e : 0, ce1 = (r1e < E) ? r1e : 0;
    const float* es0 = ES + (size_t)ce0 * 64;
    const float* es1 = ES + (size_t)ce1 * 64;

    float acc1[16][4];
#pragma unroll
    for (int j = 0; j < 16; ++j)
#pragma unroll
        for (int i = 0; i < 4; ++i) acc1[j][i] = 0.f;

    // GEMM1: [256x64] @ [64x128]; A from gmem, fp16 hi/lo split
#pragma unroll
    for (int s = 0; s < 4; ++s) {
        float2 x0a = *(const float2*)(es0 + s * 16 + 2 * t4);
        float2 x0b = *(const float2*)(es1 + s * 16 + 2 * t4);
        float2 x1a = *(const float2*)(es0 + s * 16 + 8 + 2 * t4);
        float2 x1b = *(const float2*)(es1 + s * 16 + 8 + 2 * t4);
        uint32_t ah[4], al[4];
        ah[0] = pack_hi(x0a.x, x0a.y); al[0] = pack_lo(x0a.x, x0a.y, ah[0]);
        ah[1] = pack_hi(x0b.x, x0b.y); al[1] = pack_lo(x0b.x, x0b.y, ah[1]);
        ah[2] = pack_hi(x1a.x, x1a.y); al[2] = pack_lo(x1a.x, x1a.y, ah[2]);
        ah[3] = pack_hi(x1b.x, x1b.y); al[3] = pack_lo(x1b.x, x1b.y, ah[3]);
#pragma unroll
        for (int jj = 0; jj < 8; ++jj) {
            int nrow = 8 * (2 * jj + (grp >> 1)) + rw;
            int kc = s * 16 + (grp & 1) * 8;
            uint32_t off = (uint32_t)(nrow * 72 + kc) * 2;
            uint32_t bf[4];
            ldsm4(bf, s1 + off);
            mma16816(acc1[2 * jj],     ah, bf);
            mma16816(acc1[2 * jj + 1], ah, bf + 2);
            mma16816(acc1[2 * jj],     al, bf);
            mma16816(acc1[2 * jj + 1], al, bf + 2);
        }
    }

    // silu + pack A2 fragments (frees acc1)
    uint32_t pah[8][4], pal[8][4];
#pragma unroll
    for (int s = 0; s < 8; ++s) {
        float h00 = silu_n(acc1[2 * s][0]     * 0.125f);
        float h01 = silu_n(acc1[2 * s][1]     * 0.125f);
        float h02 = silu_n(acc1[2 * s][2]     * 0.125f);
        float h03 = silu_n(acc1[2 * s][3]     * 0.125f);
        float h10 = silu_n(acc1[2 * s + 1][0] * 0.125f);
        float h11 = silu_n(acc1[2 * s + 1][1] * 0.125f);
        float h12 = silu_n(acc1[2 * s + 1][2] * 0.125f);
        float h13 = silu_n(acc1[2 * s + 1][3] * 0.125f);
        pah[s][0] = pack_hi(h00, h01); pal[s][0] = pack_lo(h00, h01, pah[s][0]);
        pah[s][1] = pack_hi(h02, h03); pal[s][1] = pack_lo(h02, h03, pah[s][1]);
        pah[s][2] = pack_hi(h10, h11); pal[s][2] = pack_lo(h10, h11, pah[s][2]);
        pah[s][3] = pack_hi(h12, h13); pal[s][3] = pack_lo(h12, h13, pah[s][3]);
    }

    // GEMM2 + fused scatter, two 64-column halves
    const float sk = 0.08838834764831845f;   // 1/sqrt(128)
#pragma unroll
    for (int half = 0; half < 2; ++half) {
        float acc2[8][4];
#pragma unroll
        for (int j = 0; j < 8; ++j)
#pragma unroll
            for (int i = 0; i < 4; ++i) acc2[j][i] = 0.f;

#pragma unroll
        for (int s = 0; s < 8; ++s) {
#pragma unroll
            for (int jj = 0; jj < 4; ++jj) {
                int nrow = half * 64 + 8 * (2 * jj + (grp >> 1)) + rw;
                int kc = s * 16 + (grp & 1) * 8;
                uint32_t off = (uint32_t)(nrow * 136 + kc) * 2;
                uint32_t bf[4];
                ldsm4(bf, s2 + off);
                mma16816(acc2[2 * jj],     pah[s], bf);
                mma16816(acc2[2 * jj + 1], pah[s], bf + 2);
                mma16816(acc2[2 * jj],     pal[s], bf);
                mma16816(acc2[2 * jj + 1], pal[s], bf + 2);
            }
        }

#pragma unroll
        for (int h = 0; h < 2; ++h) {
            int er = h ? r1e : r0e;
            if (er >= E) continue;
            int sidx = SRC[er], didx = DST[er];
            float ea = EA[er] * 0.17677669529663687f * sk;
            const float* sfr = SF + (size_t)sidx * 128 + half * 64;
            float* rfr = RF + (size_t)didx * 128 + half * 64;
#pragma unroll
            for (int j = 0; j < 8; ++j) {
                int col = 8 * j + 2 * t4;
                float2 s2v = *(const float2*)(sfr + col);
                redv2(rfr + col, acc2[j][2 * h] * ea * s2v.x, acc2[j][2 * h + 1] * ea * s2v.y);
            }
        }
    }
}

// ---------------------------------------------------------------------------
// Merged kernel: interleaved edge tiles + receiver-sc fctp tiles (3:1).
// ---------------------------------------------------------------------------
__global__ __launch_bounds__(512, 1)
void edge_and_sc(const float* __restrict__ ES,
                 const __half* __restrict__ B1, const __half* __restrict__ B2,
                 const float* __restrict__ SF, const int* __restrict__ SRC,
                 const int* __restrict__ DST, const float* __restrict__ EA,
                 float* __restrict__ RF, int E, int nEdgeTiles,
                 const float* __restrict__ Xr, const float* __restrict__ Yr,
                 const uint8_t* __restrict__ Bsc, float* __restrict__ SCout,
                 int Nr, int nScTiles)
{
    extern __shared__ uint8_t smraw[];
    const int g = blockIdx.x;
    if ((g & 3) == 3) {
        int f = g >> 2;
        if (f < nScTiles)
            fctp_body<false>(f, smraw, Xr, Yr, Bsc, SCout, nullptr, nullptr, Nr);
    } else {
        int e = g - ((g + 1) >> 2);
        if (e < nEdgeTiles)
            edge_body(e, (__half*)smraw, ES, B1, B2, SF, SRC, DST, EA, RF, E);
    }
}

// ---------------------------------------------------------------------------
// Angle: ang[n] = 0.1/32 * sum_{u,v} rf[n,u] rattr[n,v] W3[u*8+v]
// W3 staged TRANSPOSED in smem; 2 nodes per warp. (R14-proven)
// ---------------------------------------------------------------------------
__global__ __launch_bounds__(256)
void angle_kernel(const float* __restrict__ RF, const float* __restrict__ RA,
                  const float* __restrict__ W3, float* __restrict__ ANG, int N)
{
    __shared__ float w3t[8][128];
    const int tid = threadIdx.x, lane = tid & 31, wrp = tid >> 5;

    for (int i = tid; i < 1024; i += 256) {
        int u = i & 127, v = i >> 7;
        w3t[v][u] = W3[u * 8 + v];
    }
    __syncthreads();

    const int base = (blockIdx.x * 8 + wrp) * 2;
#pragma unroll
    for (int h = 0; h < 2; ++h) {
        int n = base + h;
        if (n >= N) continue;
        float ya[8];
#pragma unroll
        for (int v = 0; v < 8; ++v) ya[v] = RA[(size_t)n * 8 + v];
        float sacc = 0.f;
#pragma unroll
        for (int uu = 0; uu < 4; ++uu) {
            int u = lane + uu * 32;
            float xv = RF[(size_t)n * 128 + u];
            float w = 0.f;
#pragma unroll
            for (int v = 0; v < 8; ++v) w += ya[v] * w3t[v][u];
            sacc += xv * w;
        }
#pragma unroll
        for (int off = 16; off; off >>= 1) sacc += __shfl_xor_sync(0xffffffffu, sacc, off);
        if (lane == 0) ANG[n] = 0.003125f * sacc;   // 0.1 / 32
    }
}

// ---------------------------------------------------------------------------
extern "C" void kernel_launch(void* const* d_in, const int* in_sizes, int n_in,
                              void* d_out, int out_size)
{
    const float* sender_input   = (const float*)d_in[0];
    const float* sender_attr    = (const float*)d_in[1];
    const float* receiver_input = (const float*)d_in[2];
    const float* receiver_attr  = (const float*)d_in[3];
    const int*   edge_src       = (const int*)  d_in[4];
    const int*   edge_dst       = (const int*)  d_in[5];
    const float* edge_attr      = (const float*)d_in[6];
    const float* edge_scalars   = (const float*)d_in[7];
    const float* W_sc           = (const float*)d_in[8];
    const float* W_lin1         = (const float*)d_in[9];
    const float* W_fc1          = (const float*)d_in[10];
    const float* W_fc2          = (const float*)d_in[11];
    const float* W_lin2         = (const float*)d_in[12];
    const float* W_lin3         = (const float*)d_in[13];

    const int Ns = in_sizes[0] / 128;
    const int Nr = in_sizes[2] / 128;
    const int E  = in_sizes[4];

    float *sf_p, *sc_p, *rf_p, *ang_p;
    uint8_t* wp;
    cudaGetSymbolAddress((void**)&sf_p,  g_sf);
    cudaGetSymbolAddress((void**)&sc_p,  g_sc);
    cudaGetSymbolAddress((void**)&rf_p,  g_rf);
    cudaGetSymbolAddress((void**)&ang_p, g_ang);
    cudaGetSymbolAddress((void**)&wp,    g_wp);

    cudaFuncSetAttribute(edge_and_sc,   cudaFuncAttributeMaxDynamicSharedMemorySize, FCTP_SMEM);
    cudaFuncSetAttribute(fctp_v<false>, cudaFuncAttributeMaxDynamicSharedMemorySize, FCTP_SMEM);
    cudaFuncSetAttribute(fctp_v<true>,  cudaFuncAttributeMaxDynamicSharedMemorySize, FCTP_SMEM);

    // --- merged weight prep ---
    prep_all<<<816, 256>>>(W_fc1, W_fc2, W_lin1, W_sc, W_lin2, wp);

    cudaMemsetAsync(rf_p, 0, (size_t)Nr * 128 * sizeof(float));

    // --- sender features ---
    fctp_v<false><<<(Ns + 127) / 128, 512, FCTP_SMEM>>>(sender_input, sender_attr,
        wp + 2 * 262144, sf_p, nullptr, nullptr, Ns);

    // --- merged: edge MLP+scatter  ||  receiver self-connection fctp ---
    const int nE = (E + 255) / 256;
    const int nS = (Nr + 127) / 128;
    int grid = 4 * ((nS > (nE + 2) / 3) ? nS : (nE + 2) / 3);
    if (grid - (grid / 4) < nE + 1) grid = ((nE * 4 + 2) / 3 + 3) & ~3;
    if (grid / 4 < nS) grid = 4 * nS;
    edge_and_sc<<<grid, 512, FCTP_SMEM>>>(
        edge_scalars,
        (const __half*)wp, (const __half*)(wp + 262144),
        sf_p, edge_src, edge_dst, edge_attr, rf_p, E, nE,
        receiver_input, receiver_attr, wp + 3 * 262144, sc_p, Nr, nS);

    // --- angle + final fctp with gating epilogue ---
    angle_kernel<<<(Nr + 15) / 16, 256>>>(rf_p, receiver_attr, W_lin3, ang_p, Nr);
    fctp_v<true><<<nS, 512, FCTP_SMEM>>>(rf_p, receiver_attr,
        wp + 4 * 262144, (float*)d_out, sc_p, ang_p, Nr);
}

// round 16
// speedup vs baseline: 2.0097x; 1.2768x over previous
#include <cuda_runtime.h>
#include <cuda_fp16.h>
#include <math.h>
#include <stdint.h>

// ---------------------------------------------------------------------------
// Shapes: Ns=Nr=100000, E=600000, D=128, A=8, S=64, H=128
// Precision: fp16 single-pass (A fp16, B fp16, fp32 accum).
// Error ~2^-11 each operand -> predicted rel_err ~3e-4 < 1e-3.
// ---------------------------------------------------------------------------
#define MAX_E 600000
#define MAX_N 100000

// Scratch (__device__ globals; allocation-free rule)
__device__ float g_sf [(size_t)MAX_N * 128];   // sender features
__device__ float g_sc [(size_t)MAX_N * 128];   // receiver self connection
__device__ float g_rf [(size_t)MAX_N * 128];   // scattered receiver features
__device__ float g_ang[(size_t)MAX_N];         // receiver angle
// Prepped weights, fp16; 256KB slots.
// slot 0: fc1  n-major [n][64]
// slot 1: fc2  n-major [n][128]
// slot 2: lin1 v-major [v][n][k] (8 x 128 x 128)
// slot 3: sc   v-major
// slot 4: lin2 v-major
__device__ __align__(1024) uint8_t g_wp[5][262144];

// ---------------------------------------------------------------------------
// mma.sync / ldmatrix / cp.async helpers (sm_80+/sm_90, no arch-a gating)
// ---------------------------------------------------------------------------
__device__ __forceinline__ uint32_t smem_u32(const void* p) {
    uint32_t a;
    asm("{ .reg .u64 t; cvta.to.shared.u64 t, %1; cvt.u32.u64 %0, t; }" : "=r"(a) : "l"(p));
    return a;
}

__device__ __forceinline__ void mma16816(float* d, const uint32_t* a, const uint32_t* b) {
    asm volatile(
        "mma.sync.aligned.m16n8k16.row.col.f32.f16.f16.f32 "
        "{%0,%1,%2,%3}, {%4,%5,%6,%7}, {%8,%9}, {%0,%1,%2,%3};"
        : "+f"(d[0]), "+f"(d[1]), "+f"(d[2]), "+f"(d[3])
        : "r"(a[0]), "r"(a[1]), "r"(a[2]), "r"(a[3]), "r"(b[0]), "r"(b[1]));
}

__device__ __forceinline__ void ldsm4(uint32_t* r, uint32_t addr) {
    asm volatile("ldmatrix.sync.aligned.m8n8.x4.shared.b16 {%0,%1,%2,%3}, [%4];"
                 : "=r"(r[0]), "=r"(r[1]), "=r"(r[2]), "=r"(r[3]) : "r"(addr));
}

__device__ __forceinline__ void cp16(uint32_t s, const void* g) {
    asm volatile("cp.async.cg.shared.global [%0], [%1], 16;"
                 :: "r"(s), "l"(g) : "memory");
}
#define CP_COMMIT() asm volatile("cp.async.commit_group;" ::: "memory")
#define CP_WAIT0()  asm volatile("cp.async.wait_group 0;" ::: "memory")

// vector float2 reduction (PTX 8.1, sm_90+)
__device__ __forceinline__ void redv2(float* addr, float a, float b) {
    asm volatile("red.global.add.v2.f32 [%0], {%1, %2};" :: "l"(addr), "f"(a), "f"(b) : "memory");
}

__device__ __forceinline__ uint32_t pack_h2(float a, float b) {
    __half2 h = __floats2half2_rn(a, b);
    return *(uint32_t*)&h;
}

__device__ __forceinline__ float silu_n(float x) {
    return 1.679177f * x / (1.f + expf(-x));
}

// ---------------------------------------------------------------------------
// Merged weight prep (ONE launch): fp32 -> fp16, prepped layouts
// ---------------------------------------------------------------------------
__global__ void prep_all(const float* __restrict__ Wfc1, const float* __restrict__ Wfc2,
                         const float* __restrict__ Wl1,  const float* __restrict__ Wsc,
                         const float* __restrict__ Wl2,  uint8_t* __restrict__ wp)
{
    int idx = blockIdx.x * blockDim.x + threadIdx.x;
    if (idx < 4096) {                    // fc1 [n][64]
        int n = idx >> 5, kp = (idx & 31) << 1;
        float a = Wfc1[(size_t)kp * 128 + n];
        float b = Wfc1[(size_t)(kp + 1) * 128 + n];
        ((uint32_t*)(wp))[n * 32 + (kp >> 1)] = pack_h2(a, b);
    } else if (idx < 12288) {            // fc2 [n][128]
        int i = idx - 4096;
        int n = i >> 6, kp = (i & 63) << 1;
        float a = Wfc2[(size_t)kp * 128 + n];
        float b = Wfc2[(size_t)(kp + 1) * 128 + n];
        ((uint32_t*)(wp + 262144))[n * 64 + (kp >> 1)] = pack_h2(a, b);
    } else if (idx < 208896) {           // lin weights, v-major [v][n][k]
        int i = idx - 12288;
        int w = i >> 16;                 // 0=lin1 1=sc 2=lin2
        int r = i & 65535;
        int v = r >> 13, n = (r >> 6) & 127, up = r & 63, u = up << 1;
        const float* W = (w == 0) ? Wl1 : (w == 1) ? Wsc : Wl2;
        float a = W[(size_t)(u * 8 + v) * 128 + n];
        float b = W[(size_t)((u + 1) * 8 + v) * 128 + n];
        ((uint32_t*)(wp + (size_t)(2 + w) * 262144))[v * 8192 + n * 64 + up] = pack_h2(a, b);
    }
}

// ---------------------------------------------------------------------------
// fctp body: out[m,w] = scale * sum_v Y[m,v] * (X @ W_v)[m,w]
// Tile: 128 nodes x 128 cols, 16 warps, warp tile 32m x 32n.
// A = fp16 X (once per tile); B fp16, double-buffered. Single MMA pass.
// ---------------------------------------------------------------------------
static const int FCTP_SMEM = 108544;  // ys 4K + x 34816 + b 2x34816

template<bool COMBINE>
__device__ __forceinline__ void fctp_body(
    int tileIdx, uint8_t* smraw,
    const float* __restrict__ X, const float* __restrict__ Y,
    const uint8_t* __restrict__ Bp,   // fp16 weights, v-major
    float* __restrict__ C, const float* __restrict__ SC,
    const float* __restrict__ ANG, int N)
{
    float* ys = (float*)smraw;                            // [128][8]
    __half* xs = (__half*)(smraw + 4096);                 // [128][136]
    __half* bb = xs + 17408;                              // [2][128][136]

    const int tid = threadIdx.x, wid = tid >> 5, lane = tid & 31;
    const int q = lane >> 2, t4 = lane & 3, grp = lane >> 3, rw = lane & 7;
    const int mw = (wid & 3) * 32, nwq = (wid >> 2) * 32;
    const int r0 = tileIdx * 128;
    const uint32_t xs_a = smem_u32(xs);
    const uint32_t bb_a = smem_u32(bb);

    auto stageB = [&](int v, int b) {
        const uint8_t* sh = Bp + (size_t)v * 32768;
#pragma unroll
        for (int t = 0; t < 4; ++t) {
            int idx = tid + t * 512;
            int n = idx >> 4, seg = idx & 15;
            cp16(bb_a + (uint32_t)(b * 34816 + n * 272 + seg * 16),
                 sh + n * 256 + seg * 16);
        }
    };

    stageB(0, 0); CP_COMMIT();

    // ys
    for (int i = tid; i < 1024; i += 512) {
        int n = i >> 3, v = i & 7, r = r0 + n;
        ys[i] = (r < N) ? Y[(size_t)r * 8 + v] : 0.f;
    }

    // X -> fp16 smem (once per tile)
    {
        int m = tid >> 2, quarter = tid & 3, r = r0 + m;
        const float* xr = X + (size_t)r * 128 + quarter * 32;
#pragma unroll
        for (int g = 0; g < 4; ++g) {
            float4 f0 = make_float4(0.f, 0.f, 0.f, 0.f), f1 = f0;
            if (r < N) {
                f0 = *(const float4*)(xr + g * 8);
                f1 = *(const float4*)(xr + g * 8 + 4);
            }
            uint32_t h[4];
            h[0] = pack_h2(f0.x, f0.y);
            h[1] = pack_h2(f0.z, f0.w);
            h[2] = pack_h2(f1.x, f1.y);
            h[3] = pack_h2(f1.z, f1.w);
            int eo = m * 136 + quarter * 32 + g * 8;
            *(uint4*)(xs + eo) = make_uint4(h[0], h[1], h[2], h[3]);
        }
    }

    float fin[2][4][4];
#pragma unroll
    for (int mg = 0; mg < 2; ++mg)
#pragma unroll
        for (int j = 0; j < 4; ++j)
#pragma unroll
            for (int i = 0; i < 4; ++i) fin[mg][j][i] = 0.f;

    for (int v = 0; v < 8; ++v) {
        CP_WAIT0();
        __syncthreads();
        if (v < 7) { stageB(v + 1, (v + 1) & 1); CP_COMMIT(); }

        const int b = v & 1;
        float tmp[2][4][4];
#pragma unroll
        for (int mg = 0; mg < 2; ++mg)
#pragma unroll
            for (int j = 0; j < 4; ++j)
#pragma unroll
                for (int i = 0; i < 4; ++i) tmp[mg][j][i] = 0.f;

#pragma unroll
        for (int kc = 0; kc < 8; ++kc) {
            uint32_t ah[2][4];
#pragma unroll
            for (int mg = 0; mg < 2; ++mg) {
                uint32_t ao = (uint32_t)((mw + 16 * mg + rw + (grp & 1) * 8) * 272
                                         + (kc * 16 + (grp >> 1) * 8) * 2);
                ldsm4(ah[mg], xs_a + ao);
            }
#pragma unroll
            for (int jj = 0; jj < 2; ++jj) {
                int nrow = nwq + 8 * (2 * jj + (grp >> 1)) + rw;
                int kcol = kc * 16 + (grp & 1) * 8;
                uint32_t off = (uint32_t)(b * 34816 + nrow * 272 + kcol * 2);
                uint32_t bf[4];
                ldsm4(bf, bb_a + off);
#pragma unroll
                for (int mg = 0; mg < 2; ++mg) {
                    mma16816(tmp[mg][2 * jj],     ah[mg], bf);
                    mma16816(tmp[mg][2 * jj + 1], ah[mg], bf + 2);
                }
            }
        }

        // fp32 Y-contraction (no extra rounding)
#pragma unroll
        for (int mg = 0; mg < 2; ++mg) {
            float yva = ys[(mw + 16 * mg + q) * 8 + v];
            float yvb = ys[(mw + 16 * mg + q + 8) * 8 + v];
#pragma unroll
            for (int j = 0; j < 4; ++j) {
                fin[mg][j][0] += yva * tmp[mg][j][0];
                fin[mg][j][1] += yva * tmp[mg][j][1];
                fin[mg][j][2] += yvb * tmp[mg][j][2];
                fin[mg][j][3] += yvb * tmp[mg][j][3];
            }
        }
    }

    // epilogue
    const float sk = 0.03125f;   // 1/sqrt(128*8)
#pragma unroll
    for (int mg = 0; mg < 2; ++mg) {
#pragma unroll
        for (int h = 0; h < 2; ++h) {
            int m = r0 + mw + 16 * mg + 8 * h + q;
            if (m >= N) continue;
            float ca = 1.f, sa = 0.f;
            if (COMBINE) { float a = ANG[m]; ca = cosf(a); sa = sinf(a); }
#pragma unroll
            for (int j = 0; j < 4; ++j) {
                int col = nwq + 8 * j + 2 * t4;
                float2 val = make_float2(fin[mg][j][2 * h] * sk, fin[mg][j][2 * h + 1] * sk);
                if (COMBINE) {
                    const float* sp = SC + (size_t)m * 128 + col;
                    val.x = ca * sp[0] + sa * val.x;
                    val.y = ca * sp[1] + sa * val.y;
                }
                *(float2*)(C + (size_t)m * 128 + col) = val;
            }
        }
    }
}

template<bool COMBINE>
__global__ __launch_bounds__(512, 1)
void fctp_v(const float* __restrict__ X, const float* __restrict__ Y,
            const uint8_t* __restrict__ Bp, float* __restrict__ C,
            const float* __restrict__ SC, const float* __restrict__ ANG, int N)
{
    extern __shared__ uint8_t smraw[];
    fctp_body<COMBINE>(blockIdx.x, smraw, X, Y, Bp, C, SC, ANG, N);
}

// ---------------------------------------------------------------------------
// Edge MLP + scatter body (fp16 single-pass)
// ---------------------------------------------------------------------------
__device__ __forceinline__ void edge_body(
    int tileIdx, __half* sm,
    const float* __restrict__ ES,
    const __half* __restrict__ B1, const __half* __restrict__ B2,
    const float* __restrict__ SF, const int* __restrict__ SRC,
    const int* __restrict__ DST, const float* __restrict__ EA,
    float* __restrict__ RF, int E)
{
    __half* b1 = sm;              // [128][72]
    __half* b2 = sm + 9216;       // [128][136]

    const int tid = threadIdx.x, wid = tid >> 5, lane = tid & 31;
    const int e0 = tileIdx * 256;
    const int q = lane >> 2, t4 = lane & 3, grp = lane >> 3, rw = lane & 7;

    for (int i = tid; i < 1024; i += 512) {
        int n = i >> 3, seg = i & 7;
        *(uint4*)(b1 + n * 72 + seg * 8) = *(const uint4*)(B1 + (size_t)n * 64 + seg * 8);
    }
    for (int i = tid; i < 2048; i += 512) {
        int n = i >> 4, seg = i & 15;
        *(uint4*)(b2 + n * 136 + seg * 8) = *(const uint4*)(B2 + (size_t)n * 128 + seg * 8);
    }
    __syncthreads();

    const uint32_t s1 = smem_u32(b1), s2 = smem_u32(b2);

    const int r0e = e0 + wid * 16 + q, r1e = r0e + 8;
    const int ce0 = (r0e < E) ? r0e : 0, ce1 = (r1e < E) ? r1e : 0;
    const float* es0 = ES + (size_t)ce0 * 64;
    const float* es1 = ES + (size_t)ce1 * 64;

    float acc1[16][4];
#pragma unroll
    for (int j = 0; j < 16; ++j)
#pragma unroll
        for (int i = 0; i < 4; ++i) acc1[j][i] = 0.f;

    // GEMM1: [256x64] @ [64x128]; A from gmem (fp16 single)
#pragma unroll
    for (int s = 0; s < 4; ++s) {
        float2 x0a = *(const float2*)(es0 + s * 16 + 2 * t4);
        float2 x0b = *(const float2*)(es1 + s * 16 + 2 * t4);
        float2 x1a = *(const float2*)(es0 + s * 16 + 8 + 2 * t4);
        float2 x1b = *(const float2*)(es1 + s * 16 + 8 + 2 * t4);
        uint32_t ah[4];
        ah[0] = pack_h2(x0a.x, x0a.y);
        ah[1] = pack_h2(x0b.x, x0b.y);
        ah[2] = pack_h2(x1a.x, x1a.y);
        ah[3] = pack_h2(x1b.x, x1b.y);
#pragma unroll
        for (int jj = 0; jj < 8; ++jj) {
            int nrow = 8 * (2 * jj + (grp >> 1)) + rw;
            int kc = s * 16 + (grp & 1) * 8;
            uint32_t off = (uint32_t)(nrow * 72 + kc) * 2;
            uint32_t bf[4];
            ldsm4(bf, s1 + off);
            mma16816(acc1[2 * jj],     ah, bf);
            mma16816(acc1[2 * jj + 1], ah, bf + 2);
        }
    }

    // silu + pack A2 fragments (frees acc1)
    uint32_t pah[8][4];
#pragma unroll
    for (int s = 0; s < 8; ++s) {
        float h00 = silu_n(acc1[2 * s][0]     * 0.125f);
        float h01 = silu_n(acc1[2 * s][1]     * 0.125f);
        float h02 = silu_n(acc1[2 * s][2]     * 0.125f);
        float h03 = silu_n(acc1[2 * s][3]     * 0.125f);
        float h10 = silu_n(acc1[2 * s + 1][0] * 0.125f);
        float h11 = silu_n(acc1[2 * s + 1][1] * 0.125f);
        float h12 = silu_n(acc1[2 * s + 1][2] * 0.125f);
        float h13 = silu_n(acc1[2 * s + 1][3] * 0.125f);
        pah[s][0] = pack_h2(h00, h01);
        pah[s][1] = pack_h2(h02, h03);
        pah[s][2] = pack_h2(h10, h11);
        pah[s][3] = pack_h2(h12, h13);
    }

    // GEMM2 + fused scatter, two 64-column halves
    const float sk = 0.08838834764831845f;   // 1/sqrt(128)
#pragma unroll
    for (int half = 0; half < 2; ++half) {
        float acc2[8][4];
#pragma unroll
        for (int j = 0; j < 8; ++j)
#pragma unroll
            for (int i = 0; i < 4; ++i) acc2[j][i] = 0.f;

#pragma unroll
        for (int s = 0; s < 8; ++s) {
#pragma unroll
            for (int jj = 0; jj < 4; ++jj) {
                int nrow = half * 64 + 8 * (2 * jj + (grp >> 1)) + rw;
                int kc = s * 16 + (grp & 1) * 8;
                uint32_t off = (uint32_t)(nrow * 136 + kc) * 2;
                uint32_t bf[4];
                ldsm4(bf, s2 + off);
                mma16816(acc2[2 * jj],     pah[s], bf);
                mma16816(acc2[2 * jj + 1], pah[s], bf + 2);
            }
        }

#pragma unroll
        for (int h = 0; h < 2; ++h) {
            int er = h ? r1e : r0e;
            if (er >= E) continue;
            int sidx = SRC[er], didx = DST[er];
            float ea = EA[er] * 0.17677669529663687f * sk;
            const float* sfr = SF + (size_t)sidx * 128 + half * 64;
            float* rfr = RF + (size_t)didx * 128 + half * 64;
#pragma unroll
            for (int j = 0; j < 8; ++j) {
                int col = 8 * j + 2 * t4;
                float2 s2v = *(const float2*)(sfr + col);
                redv2(rfr + col, acc2[j][2 * h] * ea * s2v.x, acc2[j][2 * h + 1] * ea * s2v.y);
            }
        }
    }
}

// ---------------------------------------------------------------------------
// Merged kernel: interleaved edge tiles + receiver-sc fctp tiles (3:1).
// ---------------------------------------------------------------------------
__global__ __launch_bounds__(512, 1)
void edge_and_sc(const float* __restrict__ ES,
                 const __half* __restrict__ B1, const __half* __restrict__ B2,
                 const float* __restrict__ SF, const int* __restrict__ SRC,
                 const int* __restrict__ DST, const float* __restrict__ EA,
                 float* __restrict__ RF, int E, int nEdgeTiles,
                 const float* __restrict__ Xr, const float* __restrict__ Yr,
                 const uint8_t* __restrict__ Bsc, float* __restrict__ SCout,
                 int Nr, int nScTiles)
{
    extern __shared__ uint8_t smraw[];
    const int g = blockIdx.x;
    if ((g & 3) == 3) {
        int f = g >> 2;
        if (f < nScTiles)
            fctp_body<false>(f, smraw, Xr, Yr, Bsc, SCout, nullptr, nullptr, Nr);
    } else {
        int e = g - ((g + 1) >> 2);
        if (e < nEdgeTiles)
            edge_body(e, (__half*)smraw, ES, B1, B2, SF, SRC, DST, EA, RF, E);
    }
}

// ---------------------------------------------------------------------------
// Angle: ang[n] = 0.1/32 * sum_{u,v} rf[n,u] rattr[n,v] W3[u*8+v]
// W3 staged TRANSPOSED in smem; 2 nodes per warp. (R14-proven)
// ---------------------------------------------------------------------------
__global__ __launch_bounds__(256)
void angle_kernel(const float* __restrict__ RF, const float* __restrict__ RA,
                  const float* __restrict__ W3, float* __restrict__ ANG, int N)
{
    __shared__ float w3t[8][128];
    const int tid = threadIdx.x, lane = tid & 31, wrp = tid >> 5;

    for (int i = tid; i < 1024; i += 256) {
        int u = i & 127, v = i >> 7;
        w3t[v][u] = W3[u * 8 + v];
    }
    __syncthreads();

    const int base = (blockIdx.x * 8 + wrp) * 2;
#pragma unroll
    for (int h = 0; h < 2; ++h) {
        int n = base + h;
        if (n >= N) continue;
        float ya[8];
#pragma unroll
        for (int v = 0; v < 8; ++v) ya[v] = RA[(size_t)n * 8 + v];
        float sacc = 0.f;
#pragma unroll
        for (int uu = 0; uu < 4; ++uu) {
            int u = lane + uu * 32;
            float xv = RF[(size_t)n * 128 + u];
            float w = 0.f;
#pragma unroll
            for (int v = 0; v < 8; ++v) w += ya[v] * w3t[v][u];
            sacc += xv * w;
        }
#pragma unroll
        for (int off = 16; off; off >>= 1) sacc += __shfl_xor_sync(0xffffffffu, sacc, off);
        if (lane == 0) ANG[n] = 0.003125f * sacc;   // 0.1 / 32
    }
}

// ---------------------------------------------------------------------------
extern "C" void kernel_launch(void* const* d_in, const int* in_sizes, int n_in,
                              void* d_out, int out_size)
{
    const float* sender_input   = (const float*)d_in[0];
    const float* sender_attr    = (const float*)d_in[1];
    const float* receiver_input = (const float*)d_in[2];
    const float* receiver_attr  = (const float*)d_in[3];
    const int*   edge_src       = (const int*)  d_in[4];
    const int*   edge_dst       = (const int*)  d_in[5];
    const float* edge_attr      = (const float*)d_in[6];
    const float* edge_scalars   = (const float*)d_in[7];
    const float* W_sc           = (const float*)d_in[8];
    const float* W_lin1         = (const float*)d_in[9];
    const float* W_fc1          = (const float*)d_in[10];
    const float* W_fc2          = (const float*)d_in[11];
    const float* W_lin2         = (const float*)d_in[12];
    const float* W_lin3         = (const float*)d_in[13];

    const int Ns = in_sizes[0] / 128;
    const int Nr = in_sizes[2] / 128;
    const int E  = in_sizes[4];

    float *sf_p, *sc_p, *rf_p, *ang_p;
    uint8_t* wp;
    cudaGetSymbolAddress((void**)&sf_p,  g_sf);
    cudaGetSymbolAddress((void**)&sc_p,  g_sc);
    cudaGetSymbolAddress((void**)&rf_p,  g_rf);
    cudaGetSymbolAddress((void**)&ang_p, g_ang);
    cudaGetSymbolAddress((void**)&wp,    g_wp);

    cudaFuncSetAttribute(edge_and_sc,   cudaFuncAttributeMaxDynamicSharedMemorySize, FCTP_SMEM);
    cudaFuncSetAttribute(fctp_v<false>, cudaFuncAttributeMaxDynamicSharedMemorySize, FCTP_SMEM);
    cudaFuncSetAttribute(fctp_v<true>,  cudaFuncAttributeMaxDynamicSharedMemorySize, FCTP_SMEM);

    // --- merged weight prep ---
    prep_all<<<816, 256>>>(W_fc1, W_fc2, W_lin1, W_sc, W_lin2, wp);

    cudaMemsetAsync(rf_p, 0, (size_t)Nr * 128 * sizeof(float));

    // --- sender features ---
    fctp_v<false><<<(Ns + 127) / 128, 512, FCTP_SMEM>>>(sender_input, sender_attr,
        wp + 2 * 262144, sf_p, nullptr, nullptr, Ns);

    // --- merged: edge MLP+scatter  ||  receiver self-connection fctp ---
    const int nE = (E + 255) / 256;
    const int nS = (Nr + 127) / 128;
    int grid = 4 * ((nS > (nE + 2) / 3) ? nS : (nE + 2) / 3);
    if (grid - (grid / 4) < nE + 1) grid = ((nE * 4 + 2) / 3 + 3) & ~3;
    if (grid / 4 < nS) grid = 4 * nS;
    edge_and_sc<<<grid, 512, FCTP_SMEM>>>(
        edge_scalars,
        (const __half*)wp, (const __half*)(wp + 262144),
        sf_p, edge_src, edge_dst, edge_attr, rf_p, E, nE,
        receiver_input, receiver_attr, wp + 3 * 262144, sc_p, Nr, nS);

    // --- angle + final fctp with gating epilogue ---
    angle_kernel<<<(Nr + 15) / 16, 256>>>(rf_p, receiver_attr, W_lin3, ang_p, Nr);
    fctp_v<true><<<nS, 512, FCTP_SMEM>>>(rf_p, receiver_attr,
        wp + 4 * 262144, (float*)d_out, sc_p, ang_p, Nr);
}